// round 12
// baseline (speedup 1.0000x reference)
#include <cuda_runtime.h>
#include <cuda_bf16.h>
#include <cstdint>

#define BB 4
#define C 256
#define L 4096
#define EPSV 1e-5f
#define NSPLIT 4

#if defined(__CUDA_ARCH_FEAT_SM103_ALL) || defined(__CUDA_ARCH_FEAT_SM100_ALL) || defined(__CUDA_ARCH_FAMILY_SPECIFIC__)
#define TC_OK 1
#else
#define TC_OK 0
#endif

// ---------------- device scratch ----------------
__device__ float g_scale[C];
__device__ float g_shift[C];
__device__ __align__(16) __nv_bfloat16 g_wbh[4 * C * C], g_wbl[4 * C * C];
__device__ __align__(16) __nv_bfloat16 g_xth[(size_t)BB * L * C], g_xtl[(size_t)BB * L * C];
__device__ float g_s[(size_t)BB * L * L];
__device__ float g_hp[NSPLIT][(size_t)BB * C * L];
__device__ __align__(16) __nv_bfloat16 g_qh[(size_t)BB * L * C], g_ql[(size_t)BB * L * C];
__device__ __align__(16) __nv_bfloat16 g_kh[(size_t)BB * L * C], g_kl[(size_t)BB * L * C];
__device__ __align__(16) __nv_bfloat16 g_vh[(size_t)BB * C * L], g_vl[(size_t)BB * C * L];
__device__ __align__(16) __nv_bfloat16 g_ph[(size_t)BB * L * L], g_pl[(size_t)BB * L * L];
__device__ __align__(16) __nv_bfloat16 g_hth[(size_t)BB * L * C], g_htl[(size_t)BB * L * C];

// ---------------- SMEM layout: 3-stage (A 3x16KB, B 3x32KB) ----------------
#define SM_PTR   0
#define SM_MBAR0 8
#define SM_MBAR1 16
#define SM_A     1024
#define SM_B     (1024 + 49152)
#define SMEMSZ   (1024 + 49152 + 98304)

#define IDESC_BF16 0x8400490u

// ---------------- fold-proof bf16 hi/lo split ----------------
__device__ __forceinline__ void split_bf16(float v, uint16_t& hb, uint16_t& lb) {
    float hf, r;
    asm("cvt.rn.bf16.f32 %0, %1;" : "=h"(hb) : "f"(v));
    asm("cvt.f32.bf16 %0, %1;"    : "=f"(hf) : "h"(hb));
    asm("sub.rn.f32 %0, %1, %2;"  : "=f"(r)  : "f"(v), "f"(hf));
    asm("cvt.rn.bf16.f32 %0, %1;" : "=h"(lb) : "f"(r));
}
__device__ __forceinline__ void wsplit2(__nv_bfloat16* h, __nv_bfloat16* l, size_t idx,
                                        float a, float b) {
    uint16_t ha, la, hbb, lbb;
    split_bf16(a, ha, la);
    split_bf16(b, hbb, lbb);
    uint32_t hp = (uint32_t)ha | ((uint32_t)hbb << 16);
    uint32_t lp = (uint32_t)la | ((uint32_t)lbb << 16);
    *(uint32_t*)((char*)h + idx * 2) = hp;
    *(uint32_t*)((char*)l + idx * 2) = lp;
}

// ---------------- tcgen05 helpers ----------------
__device__ __forceinline__ uint32_t smem_u32(const void* p) {
    uint32_t a;
    asm("{ .reg .u64 t; cvta.to.shared.u64 t, %1; cvt.u32.u64 %0, t; }" : "=r"(a) : "l"(p));
    return a;
}
__device__ __forceinline__ uint32_t elect1() {
    uint32_t p;
    asm volatile("{\n\t.reg .pred p;\n\telect.sync _|p, 0xFFFFFFFF;\n\tselp.b32 %0, 1, 0, p;\n\t}" : "=r"(p));
    return p;
}
__device__ __forceinline__ uint64_t make_desc(uint32_t addr) {
    return (2ULL << 61) | (1ULL << 46) | (64ULL << 32) | (1ULL << 16) |
           ((uint64_t)(addr >> 4) & 0x3FFF);
}
__device__ __forceinline__ void tc_alloc(uint32_t sptr) {
#if TC_OK
    asm volatile("tcgen05.alloc.cta_group::1.sync.aligned.shared::cta.b32 [%0], %1;"
                 :: "r"(sptr), "r"(256u) : "memory");
    asm volatile("tcgen05.relinquish_alloc_permit.cta_group::1.sync.aligned;");
#endif
}
__device__ __forceinline__ void tc_dealloc(uint32_t tmem) {
#if TC_OK
    asm volatile("tcgen05.dealloc.cta_group::1.sync.aligned.b32 %0, %1;" :: "r"(tmem), "r"(256u));
#endif
}
__device__ __forceinline__ void mma_bf16(uint32_t d, uint64_t ad, uint64_t bd, bool acc) {
#if TC_OK
    uint32_t e = acc ? 1u : 0u;
    asm volatile(
        "{\n\t.reg .pred p;\n\tsetp.ne.u32 p, %4, 0;\n\t"
        "tcgen05.mma.cta_group::1.kind::f16 [%0], %1, %2, %3, {%5, %5, %5, %5}, p;\n\t}"
        :: "r"(d), "l"(ad), "l"(bd), "r"(IDESC_BF16), "r"(e), "r"(0u) : "memory");
#endif
}
__device__ __forceinline__ void tc_commit(uint32_t mbar) {
#if TC_OK
    asm volatile("tcgen05.commit.cta_group::1.mbarrier::arrive::one.shared::cluster.b64 [%0];"
                 :: "r"(mbar) : "memory");
#endif
}
__device__ __forceinline__ void tc_fence_after() {
#if TC_OK
    asm volatile("tcgen05.fence::after_thread_sync;" ::: "memory");
#endif
}
__device__ __forceinline__ void ldtm32(uint32_t* r, uint32_t addr) {
#if TC_OK
    asm volatile(
        "tcgen05.ld.sync.aligned.32x32b.x32.b32 "
        "{%0, %1, %2, %3, %4, %5, %6, %7, "
        " %8, %9, %10, %11, %12, %13, %14, %15, "
        " %16, %17, %18, %19, %20, %21, %22, %23, "
        " %24, %25, %26, %27, %28, %29, %30, %31}, [%32];"
        : "=r"(r[0]),  "=r"(r[1]),  "=r"(r[2]),  "=r"(r[3]),
          "=r"(r[4]),  "=r"(r[5]),  "=r"(r[6]),  "=r"(r[7]),
          "=r"(r[8]),  "=r"(r[9]),  "=r"(r[10]), "=r"(r[11]),
          "=r"(r[12]), "=r"(r[13]), "=r"(r[14]), "=r"(r[15]),
          "=r"(r[16]), "=r"(r[17]), "=r"(r[18]), "=r"(r[19]),
          "=r"(r[20]), "=r"(r[21]), "=r"(r[22]), "=r"(r[23]),
          "=r"(r[24]), "=r"(r[25]), "=r"(r[26]), "=r"(r[27]),
          "=r"(r[28]), "=r"(r[29]), "=r"(r[30]), "=r"(r[31])
        : "r"(addr));
    asm volatile("tcgen05.wait::ld.sync.aligned;" ::: "memory");
#else
#pragma unroll
    for (int i = 0; i < 32; i++) r[i] = 0;
#endif
}
__device__ __forceinline__ void mbar_init(uint32_t a) {
    asm volatile("mbarrier.init.shared.b64 [%0], %1;" :: "r"(a), "r"(1u) : "memory");
}
__device__ __forceinline__ void mbar_wait(uint32_t a, int parity) {
    asm volatile(
        "{\n\t.reg .pred P;\n"
        "W_%=:\n\t"
        "mbarrier.try_wait.parity.acquire.cta.shared::cta.b64 P, [%0], %1, 0x989680;\n\t"
        "@P bra.uni D_%=;\n\t"
        "bra.uni W_%=;\n"
        "D_%=:\n\t}"
        :: "r"(a), "r"(parity) : "memory");
}

// ---------------- cp.async tile loader (256 threads, SW128) ----------------
__device__ __forceinline__ void cpa_tiles(const __nv_bfloat16* __restrict__ A, int lda,
                                          const __nv_bfloat16* __restrict__ B, int ldb,
                                          int k0, uint32_t da, uint32_t db, int t) {
#pragma unroll
    for (int i = 0; i < 4; i++) {
        int idx = t + i * 256;
        int r = idx >> 3, cc = idx & 7;
        uint32_t off = r * 128 + cc * 16;
        asm volatile("cp.async.cg.shared.global [%0], [%1], 16;"
                     :: "r"(da + (off ^ ((off >> 3) & 0x70))),
                        "l"(A + (size_t)r * lda + k0 + cc * 8) : "memory");
    }
#pragma unroll
    for (int i = 0; i < 8; i++) {
        int idx = t + i * 256;
        int r = idx >> 3, cc = idx & 7;
        uint32_t off = r * 128 + cc * 16;
        asm volatile("cp.async.cg.shared.global [%0], [%1], 16;"
                     :: "r"(db + (off ^ ((off >> 3) & 0x70))),
                        "l"(B + (size_t)r * ldb + k0 + cc * 8) : "memory");
    }
}

__device__ __forceinline__ void seg_sel(const __nv_bfloat16* Ah, const __nv_bfloat16* Al,
                                        const __nv_bfloat16* Bh, const __nv_bfloat16* Bl,
                                        int ck, int nseg,
                                        const __nv_bfloat16*& Ap, const __nv_bfloat16*& Bp, int& k0) {
    int seg = (ck >= nseg) + (ck >= 2 * nseg);
    Ap = (seg == 1) ? Al : Ah;
    Bp = (seg == 2) ? Bl : Bh;
    k0 = (ck - seg * nseg) * 64;
}

// D[128x256] = Ah*Bh^T + Al*Bh^T + Ah*Bl^T   (3-stage cp.async, prefetch depth 2)
__device__ __forceinline__ uint32_t run_gemm3(const __nv_bfloat16* __restrict__ Ah,
                                              const __nv_bfloat16* __restrict__ Al,
                                              const __nv_bfloat16* __restrict__ Bh,
                                              const __nv_bfloat16* __restrict__ Bl,
                                              int lda, int ldb, int nseg, char* smem) {
    const int t = threadIdx.x;
    const int nch = 3 * nseg;
    uint32_t sb = smem_u32(smem);
    if (t < 32) tc_alloc(sb + SM_PTR);
    if (t == 0) { mbar_init(sb + SM_MBAR0); mbar_init(sb + SM_MBAR1); }
    __syncthreads();
    uint32_t tmem;
    asm volatile("ld.shared.b32 %0, [%1];" : "=r"(tmem) : "r"(sb + SM_PTR));

    int ph[2] = {0, 0};
    // prologue: prefetch chunks 0 and 1
    cpa_tiles(Ah, lda, Bh, ldb, 0, sb + SM_A, sb + SM_B, t);
    asm volatile("cp.async.commit_group;" ::: "memory");
    {
        const __nv_bfloat16 *Ap, *Bp; int k0;
        seg_sel(Ah, Al, Bh, Bl, 1, nseg, Ap, Bp, k0);
        cpa_tiles(Ap, lda, Bp, ldb, k0, sb + SM_A + 16384, sb + SM_B + 32768, t);
        asm volatile("cp.async.commit_group;" ::: "memory");
    }

    int bcur = 0;   // buffer of chunk ck
    int bpre = 2;   // buffer of chunk ck+2
    for (int ck = 0; ck < nch; ck++) {
        // free the buffer chunk ck+2 will use: MMA of chunk ck-1 must be done
        if (ck >= 1) {
            int m = (ck - 1) & 1;
            mbar_wait(sb + SM_MBAR0 + 8 * m, ph[m]);
            ph[m] ^= 1;
        }
        if (ck + 2 < nch) {
            const __nv_bfloat16 *Ap, *Bp; int k0;
            seg_sel(Ah, Al, Bh, Bl, ck + 2, nseg, Ap, Bp, k0);
            cpa_tiles(Ap, lda, Bp, ldb, k0,
                      sb + SM_A + bpre * 16384, sb + SM_B + bpre * 32768, t);
            asm volatile("cp.async.commit_group;" ::: "memory");
            asm volatile("cp.async.wait_group 2;" ::: "memory");   // chunk ck resident (FIFO)
        } else if (ck + 1 < nch) {
            asm volatile("cp.async.wait_group 1;" ::: "memory");
        } else {
            asm volatile("cp.async.wait_group 0;" ::: "memory");
        }
        __syncthreads();
        if (t < 32) {
            asm volatile("fence.proxy.async.shared::cta;" ::: "memory");
            if (elect1()) {
                uint64_t ad = make_desc(sb + SM_A + bcur * 16384);
                uint64_t bd = make_desc(sb + SM_B + bcur * 32768);
#pragma unroll
                for (int s = 0; s < 4; s++)
                    mma_bf16(tmem, ad + 2 * s, bd + 2 * s, (ck | s) != 0);
                tc_commit(sb + SM_MBAR0 + 8 * (ck & 1));
            }
        }
        bcur = (bcur == 2) ? 0 : bcur + 1;
        bpre = (bpre == 2) ? 0 : bpre + 1;
    }
    {
        int m = (nch - 1) & 1;
        mbar_wait(sb + SM_MBAR0 + 8 * m, ph[m]);
    }
    tc_fence_after();
    return tmem;
}

__device__ __forceinline__ void gemm_dealloc(uint32_t tmem) {
    __syncthreads();
    if (threadIdx.x < 32) tc_dealloc(tmem);
}

// ---------------- 1) BN stats ----------------
__global__ void __launch_bounds__(256) bn_stats(const float* __restrict__ x,
                                                const float* __restrict__ gamma,
                                                const float* __restrict__ beta) {
    int c = blockIdx.x, t = threadIdx.x;
    float s = 0.f, sq = 0.f;
    for (int b = 0; b < BB; b++) {
        const float* p = x + ((size_t)b * C + c) * L;
        for (int l = t; l < L; l += 256) { float v = p[l]; s += v; sq += v * v; }
    }
    __shared__ float sh0[256], sh1[256];
    sh0[t] = s; sh1[t] = sq;
    __syncthreads();
    for (int o = 128; o > 0; o >>= 1) {
        if (t < o) { sh0[t] += sh0[t + o]; sh1[t] += sh1[t + o]; }
        __syncthreads();
    }
    if (t == 0) {
        const float inv_n = 1.f / (float)(BB * L);
        float mean = sh0[0] * inv_n;
        float var  = sh1[0] * inv_n - mean * mean;
        float rs   = rsqrtf(var + EPSV);
        float sc   = gamma[c] * rs;
        g_scale[c] = sc;
        g_shift[c] = beta[c] - mean * sc;
    }
}

// ---------------- 2) split RAW weights ----------------
__global__ void __launch_bounds__(256) split_weights(const float* __restrict__ wq,
                                                     const float* __restrict__ wk,
                                                     const float* __restrict__ wv,
                                                     const float* __restrict__ wp) {
    int mat = blockIdx.y;
    const float* w = (mat == 0) ? wq : ((mat == 1) ? wk : ((mat == 2) ? wv : wp));
    size_t i = ((size_t)blockIdx.x * 256 + threadIdx.x) * 2;
    float2 v = *(const float2*)(w + i);
    wsplit2(g_wbh + (size_t)mat * C * C, g_wbl + (size_t)mat * C * C, i, v.x, v.y);
}

// ---------------- 3) normalize + transpose + split x ----------------
__global__ void __launch_bounds__(256) prep_xsplit(const float* __restrict__ x) {
    __shared__ float tile[32][33];
    int bi = blockIdx.z;
    int l0 = blockIdx.x * 32, c0 = blockIdx.y * 32;
    int tx = threadIdx.x, ty = threadIdx.y;
#pragma unroll
    for (int j = 0; j < 4; j++) {
        int c = c0 + ty + j * 8;
        float v = x[((size_t)bi * C + c) * L + l0 + tx];
        tile[ty + j * 8][tx] = v * g_scale[c] + g_shift[c];
    }
    __syncthreads();
#pragma unroll
    for (int j = 0; j < 4; j++) {
        int l = l0 + ty + j * 8;
        float v = tile[tx][ty + j * 8];
        uint16_t hb, lb;
        split_bf16(v, hb, lb);
        size_t idx = ((size_t)bi * L + l) * C + c0 + tx;
        *(uint16_t*)&g_xth[idx] = hb;
        *(uint16_t*)&g_xtl[idx] = lb;
    }
}

// ---------------- 4) q/k TC projection, fused split epilogue ----------------
__global__ void __launch_bounds__(256) qk_gemm_tc(const float* __restrict__ bq,
                                                  const float* __restrict__ bk) {
    extern __shared__ char smem[];
    int bi = blockIdx.y >> 1, mat = blockIdx.y & 1;
    int l0 = blockIdx.x * 128;
    size_t arow = ((size_t)bi * L + l0) * C;
    uint32_t tmem = run_gemm3(g_xth + arow, g_xtl + arow,
                              g_wbh + (size_t)mat * C * C, g_wbl + (size_t)mat * C * C, C, C, 4, smem);

    int t = threadIdx.x, wt = t & 127, wg = t >> 7;
    size_t drow = ((size_t)bi * L + l0 + wt) * C;
    __nv_bfloat16* dh = mat ? g_kh : g_qh;
    __nv_bfloat16* dl = mat ? g_kl : g_ql;
    const float* bias = mat ? bk : bq;
    for (int nbl = 0; nbl < 4; nbl++) {
        int nb = wg * 4 + nbl;
        uint32_t r[32];
        ldtm32(r, tmem + nb * 32);
#pragma unroll
        for (int j = 0; j < 16; j++) {
            int n = nb * 32 + 2 * j;
            wsplit2(dh, dl, drow + n, __uint_as_float(r[2 * j + 0]) + bias[n + 0],
                                      __uint_as_float(r[2 * j + 1]) + bias[n + 1]);
        }
    }
    gemm_dealloc(tmem);
}

// ---------------- 5) v TC projection, fused split epilogue ----------------
__global__ void __launch_bounds__(256) v_gemm_tc(const float* __restrict__ bv) {
    extern __shared__ char smem[];
    int bi = blockIdx.z, o0 = blockIdx.y * 128, l0 = blockIdx.x * 256;
    size_t brow = ((size_t)bi * L + l0) * C;
    uint32_t tmem = run_gemm3(g_wbh + 2 * C * C + o0 * C, g_wbl + 2 * C * C + o0 * C,
                              g_xth + brow, g_xtl + brow, C, C, 4, smem);

    int t = threadIdx.x, wt = t & 127, wg = t >> 7;
    float bias = bv[o0 + wt];
    size_t drow = ((size_t)bi * C + o0 + wt) * L + l0;
    for (int nbl = 0; nbl < 4; nbl++) {
        int nb = wg * 4 + nbl;
        uint32_t r[32];
        ldtm32(r, tmem + nb * 32);
#pragma unroll
        for (int j = 0; j < 16; j++) {
            int n = nb * 32 + 2 * j;
            wsplit2(g_vh, g_vl, drow + n, __uint_as_float(r[2 * j + 0]) + bias,
                                          __uint_as_float(r[2 * j + 1]) + bias);
        }
    }
    gemm_dealloc(tmem);
}

// ---------------- 6) scores TC ----------------
__global__ void __launch_bounds__(256) scores_gemm_tc() {
    extern __shared__ char smem[];
    int bi = blockIdx.z, i0 = blockIdx.y * 128, j0 = blockIdx.x * 256;
    size_t arow = ((size_t)bi * L + i0) * C;
    size_t brow = ((size_t)bi * L + j0) * C;
    uint32_t tmem = run_gemm3(g_qh + arow, g_ql + arow, g_kh + brow, g_kl + brow, C, C, 4, smem);

    int t = threadIdx.x, wt = t & 127, wg = t >> 7;
    float* dst = g_s + ((size_t)bi * L + i0 + wt) * L + j0;
    const float scale = 0.0625f;
    for (int nbl = 0; nbl < 4; nbl++) {
        int nb = wg * 4 + nbl;
        uint32_t r[32];
        ldtm32(r, tmem + nb * 32);
#pragma unroll
        for (int j = 0; j < 8; j++) {
            float4 v;
            v.x = __uint_as_float(r[4 * j + 0]) * scale;
            v.y = __uint_as_float(r[4 * j + 1]) * scale;
            v.z = __uint_as_float(r[4 * j + 2]) * scale;
            v.w = __uint_as_float(r[4 * j + 3]) * scale;
            *(float4*)(dst + nb * 32 + 4 * j) = v;
        }
    }
    gemm_dealloc(tmem);
}

// ---------------- 7) softmax rows -> ph/pl ----------------
__global__ void __launch_bounds__(256) softmax_rows() {
    size_t row = blockIdx.x;
    const float* p = g_s + row * (size_t)L;
    const int t = threadIdx.x;
    float2 r[8];
    float mx = -1e30f;
#pragma unroll
    for (int i = 0; i < 8; i++) {
        r[i] = *(const float2*)(p + i * 512 + t * 2);
        mx = fmaxf(mx, fmaxf(r[i].x, r[i].y));
    }
#pragma unroll
    for (int o = 16; o; o >>= 1) mx = fmaxf(mx, __shfl_xor_sync(0xffffffffu, mx, o));
    __shared__ float sm[8];
    if ((t & 31) == 0) sm[t >> 5] = mx;
    __syncthreads();
    float bm = sm[0];
#pragma unroll
    for (int i = 1; i < 8; i++) bm = fmaxf(bm, sm[i]);
    float s = 0.f;
#pragma unroll
    for (int i = 0; i < 8; i++) {
        r[i].x = __expf(r[i].x - bm);
        r[i].y = __expf(r[i].y - bm);
        s += r[i].x + r[i].y;
    }
#pragma unroll
    for (int o = 16; o; o >>= 1) s += __shfl_xor_sync(0xffffffffu, s, o);
    __syncthreads();
    if ((t & 31) == 0) sm[t >> 5] = s;
    __syncthreads();
    float tot = 0.f;
#pragma unroll
    for (int i = 0; i < 8; i++) tot += sm[i];
    float inv = 1.f / tot;
    size_t base = row * (size_t)L;
#pragma unroll
    for (int i = 0; i < 8; i++)
        wsplit2(g_ph, g_pl, base + i * 512 + t * 2, r[i].x * inv, r[i].y * inv);
}

// ---------------- 8) AV TC, split-K ----------------
__global__ void __launch_bounds__(256) av_gemm_tc() {
    extern __shared__ char smem[];
    int bi = blockIdx.z, ks = blockIdx.y, i0 = blockIdx.x * 128;
    const int koff = ks * (L / NSPLIT);
    size_t arow = ((size_t)bi * L + i0) * L + koff;
    size_t brow = (size_t)bi * C * L + koff;
    uint32_t tmem = run_gemm3(g_ph + arow, g_pl + arow, g_vh + brow, g_vl + brow,
                              L, L, (L / NSPLIT) / 64, smem);

    int t = threadIdx.x, wt = t & 127, wg = t >> 7;
    float* hb = g_hp[ks] + (size_t)bi * C * L;
    for (int nbl = 0; nbl < 4; nbl++) {
        int nb = wg * 4 + nbl;
        uint32_t r[32];
        ldtm32(r, tmem + nb * 32);
#pragma unroll
        for (int j = 0; j < 32; j++) {
            int c = nb * 32 + j;
            hb[(size_t)c * L + i0 + wt] = __uint_as_float(r[j]);
        }
    }
    gemm_dealloc(tmem);
}

// ---------------- 9) reduce partials + transpose + split h ----------------
__global__ void __launch_bounds__(256) reduce_split_h() {
    __shared__ float tile[32][33];
    int bi = blockIdx.z;
    int l0 = blockIdx.x * 32, c0 = blockIdx.y * 32;
    int tx = threadIdx.x, ty = threadIdx.y;
#pragma unroll
    for (int j = 0; j < 4; j++) {
        int c = c0 + ty + j * 8;
        size_t idx = ((size_t)bi * C + c) * L + l0 + tx;
        float s = g_hp[0][idx] + g_hp[1][idx] + g_hp[2][idx] + g_hp[3][idx];
        tile[ty + j * 8][tx] = s;
    }
    __syncthreads();
#pragma unroll
    for (int j = 0; j < 4; j++) {
        int l = l0 + ty + j * 8;
        float v = tile[tx][ty + j * 8];
        uint16_t hb, lb;
        split_bf16(v, hb, lb);
        size_t idx = ((size_t)bi * L + l) * C + c0 + tx;
        *(uint16_t*)&g_hth[idx] = hb;
        *(uint16_t*)&g_htl[idx] = lb;
    }
}

// ---------------- 10) proj TC + bias + residual ----------------
__global__ void __launch_bounds__(256) proj_gemm_tc(const float* __restrict__ x,
                                                    const float* __restrict__ bp,
                                                    float* __restrict__ out) {
    extern __shared__ char smem[];
    int bi = blockIdx.z, o0 = blockIdx.y * 128, l0 = blockIdx.x * 256;
    size_t brow = ((size_t)bi * L + l0) * C;
    uint32_t tmem = run_gemm3(g_wbh + 3 * C * C + o0 * C, g_wbl + 3 * C * C + o0 * C,
                              g_hth + brow, g_htl + brow, C, C, 4, smem);

    int t = threadIdx.x, wt = t & 127, wg = t >> 7;
    float bias = bp[o0 + wt];
    size_t base = ((size_t)bi * C + o0 + wt) * L + l0;
    for (int nbl = 0; nbl < 4; nbl++) {
        int nb = wg * 4 + nbl;
        uint32_t r[32];
        ldtm32(r, tmem + nb * 32);
#pragma unroll
        for (int j = 0; j < 8; j++) {
            float4 xr = *(const float4*)(x + base + nb * 32 + 4 * j);
            float4 v;
            v.x = __uint_as_float(r[4 * j + 0]) + bias + xr.x;
            v.y = __uint_as_float(r[4 * j + 1]) + bias + xr.y;
            v.z = __uint_as_float(r[4 * j + 2]) + bias + xr.z;
            v.w = __uint_as_float(r[4 * j + 3]) + bias + xr.w;
            *(float4*)(out + base + nb * 32 + 4 * j) = v;
        }
    }
    gemm_dealloc(tmem);
}

// ---------------- launch ----------------
extern "C" void kernel_launch(void* const* d_in, const int* in_sizes, int n_in,
                              void* d_out, int out_size) {
    const float* x     = (const float*)d_in[0];
    const float* gamma = (const float*)d_in[1];
    const float* beta  = (const float*)d_in[2];
    const float* wq    = (const float*)d_in[3];
    const float* bq    = (const float*)d_in[4];
    const float* wk    = (const float*)d_in[5];
    const float* bk    = (const float*)d_in[6];
    const float* wv    = (const float*)d_in[7];
    const float* bv    = (const float*)d_in[8];
    const float* wp    = (const float*)d_in[9];
    const float* bp    = (const float*)d_in[10];
    float* out = (float*)d_out;

    cudaFuncSetAttribute(qk_gemm_tc,     cudaFuncAttributeMaxDynamicSharedMemorySize, SMEMSZ);
    cudaFuncSetAttribute(v_gemm_tc,      cudaFuncAttributeMaxDynamicSharedMemorySize, SMEMSZ);
    cudaFuncSetAttribute(scores_gemm_tc, cudaFuncAttributeMaxDynamicSharedMemorySize, SMEMSZ);
    cudaFuncSetAttribute(av_gemm_tc,     cudaFuncAttributeMaxDynamicSharedMemorySize, SMEMSZ);
    cudaFuncSetAttribute(proj_gemm_tc,   cudaFuncAttributeMaxDynamicSharedMemorySize, SMEMSZ);

    bn_stats<<<C, 256>>>(x, gamma, beta);
    split_weights<<<dim3((C * C / 2) / 256, 4), 256>>>(wq, wk, wv, wp);
    prep_xsplit<<<dim3(L / 32, C / 32, BB), dim3(32, 8)>>>(x);
    qk_gemm_tc<<<dim3(L / 128, BB * 2), 256, SMEMSZ>>>(bq, bk);
    v_gemm_tc<<<dim3(L / 256, C / 128, BB), 256, SMEMSZ>>>(bv);
    scores_gemm_tc<<<dim3(L / 256, L / 128, BB), 256, SMEMSZ>>>();
    softmax_rows<<<BB * L, 256>>>();
    av_gemm_tc<<<dim3(L / 128, NSPLIT, BB), 256, SMEMSZ>>>();
    reduce_split_h<<<dim3(L / 32, C / 32, BB), dim3(32, 8)>>>();
    proj_gemm_tc<<<dim3(L / 256, C / 128, BB), 256, SMEMSZ>>>(x, bp, out);
}

// round 13
// speedup vs baseline: 1.2127x; 1.2127x over previous
#include <cuda_runtime.h>
#include <cuda_bf16.h>
#include <cstdint>

#define BB 4
#define C 256
#define L 4096
#define EPSV 1e-5f
#define NSPLIT 4

#if defined(__CUDA_ARCH_FEAT_SM103_ALL) || defined(__CUDA_ARCH_FEAT_SM100_ALL) || defined(__CUDA_ARCH_FAMILY_SPECIFIC__)
#define TC_OK 1
#else
#define TC_OK 0
#endif

// ---------------- device scratch ----------------
__device__ float g_scale[C];
__device__ float g_shift[C];
__device__ __align__(16) __nv_bfloat16 g_wbh[4 * C * C], g_wbl[4 * C * C];
__device__ __align__(16) __nv_bfloat16 g_xth[(size_t)BB * L * C], g_xtl[(size_t)BB * L * C];
__device__ float g_s[(size_t)BB * L * L];
__device__ float g_hp[NSPLIT][(size_t)BB * C * L];
__device__ __align__(16) __nv_bfloat16 g_qh[(size_t)BB * L * C], g_ql[(size_t)BB * L * C];
__device__ __align__(16) __nv_bfloat16 g_kh[(size_t)BB * L * C], g_kl[(size_t)BB * L * C];
__device__ __align__(16) __nv_bfloat16 g_vh[(size_t)BB * C * L], g_vl[(size_t)BB * C * L];
__device__ __align__(16) __nv_bfloat16 g_ph[(size_t)BB * L * L], g_pl[(size_t)BB * L * L];
__device__ __align__(16) __nv_bfloat16 g_hth[(size_t)BB * L * C], g_htl[(size_t)BB * L * C];

// ---------------- SMEM layout (R10: 2-buffer, 97KB, 2 CTAs/SM) ----------------
#define SM_PTR   0
#define SM_MBAR0 8
#define SM_MBAR1 16
#define SM_A     1024
#define SM_B     (1024 + 32768)
#define SMEMSZ   (1024 + 32768 + 65536)

#define IDESC_BF16 0x8400490u

// ---------------- fold-proof bf16 hi/lo split ----------------
__device__ __forceinline__ void split_bf16(float v, uint16_t& hb, uint16_t& lb) {
    float hf, r;
    asm("cvt.rn.bf16.f32 %0, %1;" : "=h"(hb) : "f"(v));
    asm("cvt.f32.bf16 %0, %1;"    : "=f"(hf) : "h"(hb));
    asm("sub.rn.f32 %0, %1, %2;"  : "=f"(r)  : "f"(v), "f"(hf));
    asm("cvt.rn.bf16.f32 %0, %1;" : "=h"(lb) : "f"(r));
}
__device__ __forceinline__ void wsplit2(__nv_bfloat16* h, __nv_bfloat16* l, size_t idx,
                                        float a, float b) {
    uint16_t ha, la, hbb, lbb;
    split_bf16(a, ha, la);
    split_bf16(b, hbb, lbb);
    uint32_t hp = (uint32_t)ha | ((uint32_t)hbb << 16);
    uint32_t lp = (uint32_t)la | ((uint32_t)lbb << 16);
    *(uint32_t*)((char*)h + idx * 2) = hp;
    *(uint32_t*)((char*)l + idx * 2) = lp;
}

// ---------------- tcgen05 helpers ----------------
__device__ __forceinline__ uint32_t smem_u32(const void* p) {
    uint32_t a;
    asm("{ .reg .u64 t; cvta.to.shared.u64 t, %1; cvt.u32.u64 %0, t; }" : "=r"(a) : "l"(p));
    return a;
}
__device__ __forceinline__ uint32_t elect1() {
    uint32_t p;
    asm volatile("{\n\t.reg .pred p;\n\telect.sync _|p, 0xFFFFFFFF;\n\tselp.b32 %0, 1, 0, p;\n\t}" : "=r"(p));
    return p;
}
__device__ __forceinline__ uint64_t make_desc(uint32_t addr) {
    return (2ULL << 61) | (1ULL << 46) | (64ULL << 32) | (1ULL << 16) |
           ((uint64_t)(addr >> 4) & 0x3FFF);
}
__device__ __forceinline__ void tc_alloc(uint32_t sptr) {
#if TC_OK
    asm volatile("tcgen05.alloc.cta_group::1.sync.aligned.shared::cta.b32 [%0], %1;"
                 :: "r"(sptr), "r"(256u) : "memory");
    asm volatile("tcgen05.relinquish_alloc_permit.cta_group::1.sync.aligned;");
#endif
}
__device__ __forceinline__ void tc_dealloc(uint32_t tmem) {
#if TC_OK
    asm volatile("tcgen05.dealloc.cta_group::1.sync.aligned.b32 %0, %1;" :: "r"(tmem), "r"(256u));
#endif
}
__device__ __forceinline__ void mma_bf16(uint32_t d, uint64_t ad, uint64_t bd, bool acc) {
#if TC_OK
    uint32_t e = acc ? 1u : 0u;
    asm volatile(
        "{\n\t.reg .pred p;\n\tsetp.ne.u32 p, %4, 0;\n\t"
        "tcgen05.mma.cta_group::1.kind::f16 [%0], %1, %2, %3, {%5, %5, %5, %5}, p;\n\t}"
        :: "r"(d), "l"(ad), "l"(bd), "r"(IDESC_BF16), "r"(e), "r"(0u) : "memory");
#endif
}
__device__ __forceinline__ void tc_commit(uint32_t mbar) {
#if TC_OK
    asm volatile("tcgen05.commit.cta_group::1.mbarrier::arrive::one.shared::cluster.b64 [%0];"
                 :: "r"(mbar) : "memory");
#endif
}
__device__ __forceinline__ void tc_fence_after() {
#if TC_OK
    asm volatile("tcgen05.fence::after_thread_sync;" ::: "memory");
#endif
}
__device__ __forceinline__ void ldtm32(uint32_t* r, uint32_t addr) {
#if TC_OK
    asm volatile(
        "tcgen05.ld.sync.aligned.32x32b.x32.b32 "
        "{%0, %1, %2, %3, %4, %5, %6, %7, "
        " %8, %9, %10, %11, %12, %13, %14, %15, "
        " %16, %17, %18, %19, %20, %21, %22, %23, "
        " %24, %25, %26, %27, %28, %29, %30, %31}, [%32];"
        : "=r"(r[0]),  "=r"(r[1]),  "=r"(r[2]),  "=r"(r[3]),
          "=r"(r[4]),  "=r"(r[5]),  "=r"(r[6]),  "=r"(r[7]),
          "=r"(r[8]),  "=r"(r[9]),  "=r"(r[10]), "=r"(r[11]),
          "=r"(r[12]), "=r"(r[13]), "=r"(r[14]), "=r"(r[15]),
          "=r"(r[16]), "=r"(r[17]), "=r"(r[18]), "=r"(r[19]),
          "=r"(r[20]), "=r"(r[21]), "=r"(r[22]), "=r"(r[23]),
          "=r"(r[24]), "=r"(r[25]), "=r"(r[26]), "=r"(r[27]),
          "=r"(r[28]), "=r"(r[29]), "=r"(r[30]), "=r"(r[31])
        : "r"(addr));
    asm volatile("tcgen05.wait::ld.sync.aligned;" ::: "memory");
#else
#pragma unroll
    for (int i = 0; i < 32; i++) r[i] = 0;
#endif
}
__device__ __forceinline__ void mbar_init(uint32_t a) {
    asm volatile("mbarrier.init.shared.b64 [%0], %1;" :: "r"(a), "r"(1u) : "memory");
}
__device__ __forceinline__ void mbar_wait(uint32_t a, int parity) {
    asm volatile(
        "{\n\t.reg .pred P;\n"
        "W_%=:\n\t"
        "mbarrier.try_wait.parity.acquire.cta.shared::cta.b64 P, [%0], %1, 0x989680;\n\t"
        "@P bra.uni D_%=;\n\t"
        "bra.uni W_%=;\n"
        "D_%=:\n\t}"
        :: "r"(a), "r"(parity) : "memory");
}

// ---------------- cp.async tile loader (256 threads, SW128) ----------------
__device__ __forceinline__ void cpa_tiles(const __nv_bfloat16* __restrict__ A, int lda,
                                          const __nv_bfloat16* __restrict__ B, int ldb,
                                          int k0, uint32_t da, uint32_t db, int t) {
#pragma unroll
    for (int i = 0; i < 4; i++) {
        int idx = t + i * 256;
        int r = idx >> 3, cc = idx & 7;
        uint32_t off = r * 128 + cc * 16;
        asm volatile("cp.async.cg.shared.global [%0], [%1], 16;"
                     :: "r"(da + (off ^ ((off >> 3) & 0x70))),
                        "l"(A + (size_t)r * lda + k0 + cc * 8) : "memory");
    }
#pragma unroll
    for (int i = 0; i < 8; i++) {
        int idx = t + i * 256;
        int r = idx >> 3, cc = idx & 7;
        uint32_t off = r * 128 + cc * 16;
        asm volatile("cp.async.cg.shared.global [%0], [%1], 16;"
                     :: "r"(db + (off ^ ((off >> 3) & 0x70))),
                        "l"(B + (size_t)r * ldb + k0 + cc * 8) : "memory");
    }
}

__device__ __forceinline__ void seg_sel(const __nv_bfloat16* Ah, const __nv_bfloat16* Al,
                                        const __nv_bfloat16* Bh, const __nv_bfloat16* Bl,
                                        int ck, int nseg,
                                        const __nv_bfloat16*& Ap, const __nv_bfloat16*& Bp, int& k0) {
    int seg = (ck >= nseg) + (ck >= 2 * nseg);
    Ap = (seg == 1) ? Al : Ah;
    Bp = (seg == 2) ? Bl : Bh;
    k0 = (ck - seg * nseg) * 64;
}

// D[128x256] = Ah*Bh^T + Al*Bh^T + Ah*Bl^T   (R10 2-buffer cp.async pipeline)
__device__ __forceinline__ uint32_t run_gemm3(const __nv_bfloat16* __restrict__ Ah,
                                              const __nv_bfloat16* __restrict__ Al,
                                              const __nv_bfloat16* __restrict__ Bh,
                                              const __nv_bfloat16* __restrict__ Bl,
                                              int lda, int ldb, int nseg, char* smem) {
    const int t = threadIdx.x;
    const int nch = 3 * nseg;
    uint32_t sb = smem_u32(smem);
    if (t < 32) tc_alloc(sb + SM_PTR);
    if (t == 0) { mbar_init(sb + SM_MBAR0); mbar_init(sb + SM_MBAR1); }
    __syncthreads();
    uint32_t tmem;
    asm volatile("ld.shared.b32 %0, [%1];" : "=r"(tmem) : "r"(sb + SM_PTR));

    int ph0 = 0, ph1 = 0;
    cpa_tiles(Ah, lda, Bh, ldb, 0, sb + SM_A, sb + SM_B, t);
    asm volatile("cp.async.commit_group;" ::: "memory");

    for (int ck = 0; ck < nch; ck++) {
        const int pb = ck & 1;
        if (ck + 1 < nch) {
            const int nb = pb ^ 1;
            if (ck >= 1) {
                if (nb == 0) { mbar_wait(sb + SM_MBAR0, ph0); ph0 ^= 1; }
                else         { mbar_wait(sb + SM_MBAR1, ph1); ph1 ^= 1; }
            }
            const __nv_bfloat16 *Ap, *Bp;
            int k0;
            seg_sel(Ah, Al, Bh, Bl, ck + 1, nseg, Ap, Bp, k0);
            cpa_tiles(Ap, lda, Bp, ldb, k0,
                      sb + SM_A + nb * 16384, sb + SM_B + nb * 32768, t);
            asm volatile("cp.async.commit_group;" ::: "memory");
            asm volatile("cp.async.wait_group 1;" ::: "memory");
        } else {
            asm volatile("cp.async.wait_group 0;" ::: "memory");
        }
        __syncthreads();
        if (t < 32) {
            asm volatile("fence.proxy.async.shared::cta;" ::: "memory");
            if (elect1()) {
                uint64_t ad = make_desc(sb + SM_A + pb * 16384);
                uint64_t bd = make_desc(sb + SM_B + pb * 32768);
#pragma unroll
                for (int s = 0; s < 4; s++)
                    mma_bf16(tmem, ad + 2 * s, bd + 2 * s, (ck | s) != 0);
                tc_commit(sb + SM_MBAR0 + pb * 8);
            }
        }
    }
    if (((nch - 1) & 1) == 0) mbar_wait(sb + SM_MBAR0, ph0);
    else                      mbar_wait(sb + SM_MBAR1, ph1);
    tc_fence_after();
    return tmem;
}

__device__ __forceinline__ void gemm_dealloc(uint32_t tmem) {
    __syncthreads();
    if (threadIdx.x < 32) tc_dealloc(tmem);
}

// ---------------- 1) BN stats ----------------
__global__ void __launch_bounds__(256) bn_stats(const float* __restrict__ x,
                                                const float* __restrict__ gamma,
                                                const float* __restrict__ beta) {
    int c = blockIdx.x, t = threadIdx.x;
    float s = 0.f, sq = 0.f;
    for (int b = 0; b < BB; b++) {
        const float* p = x + ((size_t)b * C + c) * L;
        for (int l = t; l < L; l += 256) { float v = p[l]; s += v; sq += v * v; }
    }
    __shared__ float sh0[256], sh1[256];
    sh0[t] = s; sh1[t] = sq;
    __syncthreads();
    for (int o = 128; o > 0; o >>= 1) {
        if (t < o) { sh0[t] += sh0[t + o]; sh1[t] += sh1[t + o]; }
        __syncthreads();
    }
    if (t == 0) {
        const float inv_n = 1.f / (float)(BB * L);
        float mean = sh0[0] * inv_n;
        float var  = sh1[0] * inv_n - mean * mean;
        float rs   = rsqrtf(var + EPSV);
        float sc   = gamma[c] * rs;
        g_scale[c] = sc;
        g_shift[c] = beta[c] - mean * sc;
    }
}

// ---------------- 2) split RAW weights ----------------
__global__ void __launch_bounds__(256) split_weights(const float* __restrict__ wq,
                                                     const float* __restrict__ wk,
                                                     const float* __restrict__ wv,
                                                     const float* __restrict__ wp) {
    int mat = blockIdx.y;
    const float* w = (mat == 0) ? wq : ((mat == 1) ? wk : ((mat == 2) ? wv : wp));
    size_t i = ((size_t)blockIdx.x * 256 + threadIdx.x) * 2;
    float2 v = *(const float2*)(w + i);
    wsplit2(g_wbh + (size_t)mat * C * C, g_wbl + (size_t)mat * C * C, i, v.x, v.y);
}

// ---------------- 3) normalize + transpose + split x ----------------
__global__ void __launch_bounds__(256) prep_xsplit(const float* __restrict__ x) {
    __shared__ float tile[32][33];
    int bi = blockIdx.z;
    int l0 = blockIdx.x * 32, c0 = blockIdx.y * 32;
    int tx = threadIdx.x, ty = threadIdx.y;
#pragma unroll
    for (int j = 0; j < 4; j++) {
        int c = c0 + ty + j * 8;
        float v = x[((size_t)bi * C + c) * L + l0 + tx];
        tile[ty + j * 8][tx] = v * g_scale[c] + g_shift[c];
    }
    __syncthreads();
#pragma unroll
    for (int j = 0; j < 4; j++) {
        int l = l0 + ty + j * 8;
        float v = tile[tx][ty + j * 8];
        uint16_t hb, lb;
        split_bf16(v, hb, lb);
        size_t idx = ((size_t)bi * L + l) * C + c0 + tx;
        *(uint16_t*)&g_xth[idx] = hb;
        *(uint16_t*)&g_xtl[idx] = lb;
    }
}

// ---------------- 4) q/k TC projection, fused split epilogue ----------------
__global__ void __launch_bounds__(256) qk_gemm_tc(const float* __restrict__ bq,
                                                  const float* __restrict__ bk) {
    extern __shared__ char smem[];
    int bi = blockIdx.y >> 1, mat = blockIdx.y & 1;
    int l0 = blockIdx.x * 128;
    size_t arow = ((size_t)bi * L + l0) * C;
    uint32_t tmem = run_gemm3(g_xth + arow, g_xtl + arow,
                              g_wbh + (size_t)mat * C * C, g_wbl + (size_t)mat * C * C, C, C, 4, smem);

    int t = threadIdx.x, wt = t & 127, wg = t >> 7;
    size_t drow = ((size_t)bi * L + l0 + wt) * C;
    __nv_bfloat16* dh = mat ? g_kh : g_qh;
    __nv_bfloat16* dl = mat ? g_kl : g_ql;
    const float* bias = mat ? bk : bq;
    for (int nbl = 0; nbl < 4; nbl++) {
        int nb = wg * 4 + nbl;
        uint32_t r[32];
        ldtm32(r, tmem + nb * 32);
#pragma unroll
        for (int j = 0; j < 16; j++) {
            int n = nb * 32 + 2 * j;
            wsplit2(dh, dl, drow + n, __uint_as_float(r[2 * j + 0]) + bias[n + 0],
                                      __uint_as_float(r[2 * j + 1]) + bias[n + 1]);
        }
    }
    gemm_dealloc(tmem);
}

// ---------------- 5) v TC projection, fused split epilogue ----------------
__global__ void __launch_bounds__(256) v_gemm_tc(const float* __restrict__ bv) {
    extern __shared__ char smem[];
    int bi = blockIdx.z, o0 = blockIdx.y * 128, l0 = blockIdx.x * 256;
    size_t brow = ((size_t)bi * L + l0) * C;
    uint32_t tmem = run_gemm3(g_wbh + 2 * C * C + o0 * C, g_wbl + 2 * C * C + o0 * C,
                              g_xth + brow, g_xtl + brow, C, C, 4, smem);

    int t = threadIdx.x, wt = t & 127, wg = t >> 7;
    float bias = bv[o0 + wt];
    size_t drow = ((size_t)bi * C + o0 + wt) * L + l0;
    for (int nbl = 0; nbl < 4; nbl++) {
        int nb = wg * 4 + nbl;
        uint32_t r[32];
        ldtm32(r, tmem + nb * 32);
#pragma unroll
        for (int j = 0; j < 16; j++) {
            int n = nb * 32 + 2 * j;
            wsplit2(g_vh, g_vl, drow + n, __uint_as_float(r[2 * j + 0]) + bias,
                                          __uint_as_float(r[2 * j + 1]) + bias);
        }
    }
    gemm_dealloc(tmem);
}

// ---------------- 6) scores TC (per-batch) ----------------
__global__ void __launch_bounds__(256) scores_gemm_tc(int bi0) {
    extern __shared__ char smem[];
    int bi = bi0, i0 = blockIdx.y * 128, j0 = blockIdx.x * 256;
    size_t arow = ((size_t)bi * L + i0) * C;
    size_t brow = ((size_t)bi * L + j0) * C;
    uint32_t tmem = run_gemm3(g_qh + arow, g_ql + arow, g_kh + brow, g_kl + brow, C, C, 4, smem);

    int t = threadIdx.x, wt = t & 127, wg = t >> 7;
    float* dst = g_s + ((size_t)bi * L + i0 + wt) * L + j0;
    const float scale = 0.0625f;
    for (int nbl = 0; nbl < 4; nbl++) {
        int nb = wg * 4 + nbl;
        uint32_t r[32];
        ldtm32(r, tmem + nb * 32);
#pragma unroll
        for (int j = 0; j < 8; j++) {
            float4 v;
            v.x = __uint_as_float(r[4 * j + 0]) * scale;
            v.y = __uint_as_float(r[4 * j + 1]) * scale;
            v.z = __uint_as_float(r[4 * j + 2]) * scale;
            v.w = __uint_as_float(r[4 * j + 3]) * scale;
            *(float4*)(dst + nb * 32 + 4 * j) = v;
        }
    }
    gemm_dealloc(tmem);
}

// ---------------- 7) softmax rows (per-batch) -> ph/pl ----------------
__global__ void __launch_bounds__(256) softmax_rows(int bi0) {
    size_t row = (size_t)bi0 * L + blockIdx.x;
    const float* p = g_s + row * (size_t)L;
    const int t = threadIdx.x;
    float2 r[8];
    float mx = -1e30f;
#pragma unroll
    for (int i = 0; i < 8; i++) {
        r[i] = *(const float2*)(p + i * 512 + t * 2);
        mx = fmaxf(mx, fmaxf(r[i].x, r[i].y));
    }
#pragma unroll
    for (int o = 16; o; o >>= 1) mx = fmaxf(mx, __shfl_xor_sync(0xffffffffu, mx, o));
    __shared__ float sm[8];
    if ((t & 31) == 0) sm[t >> 5] = mx;
    __syncthreads();
    float bm = sm[0];
#pragma unroll
    for (int i = 1; i < 8; i++) bm = fmaxf(bm, sm[i]);
    float s = 0.f;
#pragma unroll
    for (int i = 0; i < 8; i++) {
        r[i].x = __expf(r[i].x - bm);
        r[i].y = __expf(r[i].y - bm);
        s += r[i].x + r[i].y;
    }
#pragma unroll
    for (int o = 16; o; o >>= 1) s += __shfl_xor_sync(0xffffffffu, s, o);
    __syncthreads();
    if ((t & 31) == 0) sm[t >> 5] = s;
    __syncthreads();
    float tot = 0.f;
#pragma unroll
    for (int i = 0; i < 8; i++) tot += sm[i];
    float inv = 1.f / tot;
    size_t base = row * (size_t)L;
#pragma unroll
    for (int i = 0; i < 8; i++)
        wsplit2(g_ph, g_pl, base + i * 512 + t * 2, r[i].x * inv, r[i].y * inv);
}

// ---------------- 8) AV TC, split-K (per-batch) ----------------
__global__ void __launch_bounds__(256) av_gemm_tc(int bi0) {
    extern __shared__ char smem[];
    int bi = bi0, ks = blockIdx.y, i0 = blockIdx.x * 128;
    const int koff = ks * (L / NSPLIT);
    size_t arow = ((size_t)bi * L + i0) * L + koff;
    size_t brow = (size_t)bi * C * L + koff;
    uint32_t tmem = run_gemm3(g_ph + arow, g_pl + arow, g_vh + brow, g_vl + brow,
                              L, L, (L / NSPLIT) / 64, smem);

    int t = threadIdx.x, wt = t & 127, wg = t >> 7;
    float* hb = g_hp[ks] + (size_t)bi * C * L;
    for (int nbl = 0; nbl < 4; nbl++) {
        int nb = wg * 4 + nbl;
        uint32_t r[32];
        ldtm32(r, tmem + nb * 32);
#pragma unroll
        for (int j = 0; j < 32; j++) {
            int c = nb * 32 + j;
            hb[(size_t)c * L + i0 + wt] = __uint_as_float(r[j]);
        }
    }
    gemm_dealloc(tmem);
}

// ---------------- 9) reduce partials + transpose + split h ----------------
__global__ void __launch_bounds__(256) reduce_split_h() {
    __shared__ float tile[32][33];
    int bi = blockIdx.z;
    int l0 = blockIdx.x * 32, c0 = blockIdx.y * 32;
    int tx = threadIdx.x, ty = threadIdx.y;
#pragma unroll
    for (int j = 0; j < 4; j++) {
        int c = c0 + ty + j * 8;
        size_t idx = ((size_t)bi * C + c) * L + l0 + tx;
        float s = g_hp[0][idx] + g_hp[1][idx] + g_hp[2][idx] + g_hp[3][idx];
        tile[ty + j * 8][tx] = s;
    }
    __syncthreads();
#pragma unroll
    for (int j = 0; j < 4; j++) {
        int l = l0 + ty + j * 8;
        float v = tile[tx][ty + j * 8];
        uint16_t hb, lb;
        split_bf16(v, hb, lb);
        size_t idx = ((size_t)bi * L + l) * C + c0 + tx;
        *(uint16_t*)&g_hth[idx] = hb;
        *(uint16_t*)&g_htl[idx] = lb;
    }
}

// ---------------- 10) proj TC + bias + residual ----------------
__global__ void __launch_bounds__(256) proj_gemm_tc(const float* __restrict__ x,
                                                    const float* __restrict__ bp,
                                                    float* __restrict__ out) {
    extern __shared__ char smem[];
    int bi = blockIdx.z, o0 = blockIdx.y * 128, l0 = blockIdx.x * 256;
    size_t brow = ((size_t)bi * L + l0) * C;
    uint32_t tmem = run_gemm3(g_wbh + 3 * C * C + o0 * C, g_wbl + 3 * C * C + o0 * C,
                              g_hth + brow, g_htl + brow, C, C, 4, smem);

    int t = threadIdx.x, wt = t & 127, wg = t >> 7;
    float bias = bp[o0 + wt];
    size_t base = ((size_t)bi * C + o0 + wt) * L + l0;
    for (int nbl = 0; nbl < 4; nbl++) {
        int nb = wg * 4 + nbl;
        uint32_t r[32];
        ldtm32(r, tmem + nb * 32);
#pragma unroll
        for (int j = 0; j < 8; j++) {
            float4 xr = *(const float4*)(x + base + nb * 32 + 4 * j);
            float4 v;
            v.x = __uint_as_float(r[4 * j + 0]) + bias + xr.x;
            v.y = __uint_as_float(r[4 * j + 1]) + bias + xr.y;
            v.z = __uint_as_float(r[4 * j + 2]) + bias + xr.z;
            v.w = __uint_as_float(r[4 * j + 3]) + bias + xr.w;
            *(float4*)(out + base + nb * 32 + 4 * j) = v;
        }
    }
    gemm_dealloc(tmem);
}

// ---------------- launch: forked multi-stream graph ----------------
extern "C" void kernel_launch(void* const* d_in, const int* in_sizes, int n_in,
                              void* d_out, int out_size) {
    const float* x     = (const float*)d_in[0];
    const float* gamma = (const float*)d_in[1];
    const float* beta  = (const float*)d_in[2];
    const float* wq    = (const float*)d_in[3];
    const float* bq    = (const float*)d_in[4];
    const float* wk    = (const float*)d_in[5];
    const float* bk    = (const float*)d_in[6];
    const float* wv    = (const float*)d_in[7];
    const float* bv    = (const float*)d_in[8];
    const float* wp    = (const float*)d_in[9];
    const float* bp    = (const float*)d_in[10];
    float* out = (float*)d_out;

    static bool inited = false;
    static cudaStream_t s1, s2, s3;
    static cudaEvent_t e0, ePrep, eW, eQK, eV, eC1, eC2, eC3;
    if (!inited) {
        cudaStreamCreateWithFlags(&s1, cudaStreamNonBlocking);
        cudaStreamCreateWithFlags(&s2, cudaStreamNonBlocking);
        cudaStreamCreateWithFlags(&s3, cudaStreamNonBlocking);
        cudaEventCreateWithFlags(&e0,    cudaEventDisableTiming);
        cudaEventCreateWithFlags(&ePrep, cudaEventDisableTiming);
        cudaEventCreateWithFlags(&eW,    cudaEventDisableTiming);
        cudaEventCreateWithFlags(&eQK,   cudaEventDisableTiming);
        cudaEventCreateWithFlags(&eV,    cudaEventDisableTiming);
        cudaEventCreateWithFlags(&eC1,   cudaEventDisableTiming);
        cudaEventCreateWithFlags(&eC2,   cudaEventDisableTiming);
        cudaEventCreateWithFlags(&eC3,   cudaEventDisableTiming);
        cudaFuncSetAttribute(qk_gemm_tc,     cudaFuncAttributeMaxDynamicSharedMemorySize, SMEMSZ);
        cudaFuncSetAttribute(v_gemm_tc,      cudaFuncAttributeMaxDynamicSharedMemorySize, SMEMSZ);
        cudaFuncSetAttribute(scores_gemm_tc, cudaFuncAttributeMaxDynamicSharedMemorySize, SMEMSZ);
        cudaFuncSetAttribute(av_gemm_tc,     cudaFuncAttributeMaxDynamicSharedMemorySize, SMEMSZ);
        cudaFuncSetAttribute(proj_gemm_tc,   cudaFuncAttributeMaxDynamicSharedMemorySize, SMEMSZ);
        inited = true;
    }

    // fork: split_weights on s1 (independent of BN)
    cudaEventRecord(e0, 0);
    cudaStreamWaitEvent(s1, e0, 0);
    split_weights<<<dim3((C * C / 2) / 256, 4), 256, 0, s1>>>(wq, wk, wv, wp);
    cudaEventRecord(eW, s1);

    // main stream: BN -> prep
    bn_stats<<<C, 256>>>(x, gamma, beta);
    prep_xsplit<<<dim3(L / 32, C / 32, BB), dim3(32, 8)>>>(x);
    cudaEventRecord(ePrep, 0);

    // qk on s0 (needs prep + weights); v on s1 (needs prep, weights already in-stream)
    cudaStreamWaitEvent(0, eW, 0);
    qk_gemm_tc<<<dim3(L / 128, BB * 2), 256, SMEMSZ, 0>>>(bq, bk);
    cudaEventRecord(eQK, 0);

    cudaStreamWaitEvent(s1, ePrep, 0);
    v_gemm_tc<<<dim3(L / 256, C / 128, BB), 256, SMEMSZ, s1>>>(bv);
    cudaEventRecord(eV, s1);

    // per-batch chains: scores(b) -> softmax(b) -> av(b)
    // b=0 on s0 (qk already in-stream; wait v)
    cudaStreamWaitEvent(0, eV, 0);
    scores_gemm_tc<<<dim3(L / 256, L / 128, 1), 256, SMEMSZ, 0>>>(0);
    softmax_rows<<<L, 256, 0, 0>>>(0);
    av_gemm_tc<<<dim3(L / 128, NSPLIT, 1), 256, SMEMSZ, 0>>>(0);

    // b=1 on s1 (v in-stream; wait qk)
    cudaStreamWaitEvent(s1, eQK, 0);
    scores_gemm_tc<<<dim3(L / 256, L / 128, 1), 256, SMEMSZ, s1>>>(1);
    softmax_rows<<<L, 256, 0, s1>>>(1);
    av_gemm_tc<<<dim3(L / 128, NSPLIT, 1), 256, SMEMSZ, s1>>>(1);
    cudaEventRecord(eC1, s1);

    // b=2 on s2 (wait qk + v)
    cudaStreamWaitEvent(s2, eQK, 0);
    cudaStreamWaitEvent(s2, eV, 0);
    scores_gemm_tc<<<dim3(L / 256, L / 128, 1), 256, SMEMSZ, s2>>>(2);
    softmax_rows<<<L, 256, 0, s2>>>(2);
    av_gemm_tc<<<dim3(L / 128, NSPLIT, 1), 256, SMEMSZ, s2>>>(2);
    cudaEventRecord(eC2, s2);

    // b=3 on s3 (wait qk + v)
    cudaStreamWaitEvent(s3, eQK, 0);
    cudaStreamWaitEvent(s3, eV, 0);
    scores_gemm_tc<<<dim3(L / 256, L / 128, 1), 256, SMEMSZ, s3>>>(3);
    softmax_rows<<<L, 256, 0, s3>>>(3);
    av_gemm_tc<<<dim3(L / 128, NSPLIT, 1), 256, SMEMSZ, s3>>>(3);
    cudaEventRecord(eC3, s3);

    // join -> reduce + proj on s0
    cudaStreamWaitEvent(0, eC1, 0);
    cudaStreamWaitEvent(0, eC2, 0);
    cudaStreamWaitEvent(0, eC3, 0);
    reduce_split_h<<<dim3(L / 32, C / 32, BB), dim3(32, 8)>>>();
    proj_gemm_tc<<<dim3(L / 256, C / 128, BB), 256, SMEMSZ>>>(x, bp, out);
}

// round 14
// speedup vs baseline: 1.2604x; 1.0393x over previous
#include <cuda_runtime.h>
#include <cuda_bf16.h>
#include <cuda.h>
#include <cstdint>

#define BB 4
#define C 256
#define L 4096
#define EPSV 1e-5f
#define NSPLIT 4

#if defined(__CUDA_ARCH_FEAT_SM103_ALL) || defined(__CUDA_ARCH_FEAT_SM100_ALL) || defined(__CUDA_ARCH_FAMILY_SPECIFIC__)
#define TC_OK 1
#else
#define TC_OK 0
#endif

// ---------------- device scratch ----------------
__device__ float g_scale[C];
__device__ float g_shift[C];
__device__ __align__(16) __nv_bfloat16 g_wbh[4 * C * C], g_wbl[4 * C * C];
__device__ __align__(16) __nv_bfloat16 g_xth[(size_t)BB * L * C], g_xtl[(size_t)BB * L * C];
__device__ float g_s[(size_t)BB * L * L];
__device__ float g_hp[NSPLIT][(size_t)BB * C * L];
__device__ __align__(16) __nv_bfloat16 g_qh[(size_t)BB * L * C], g_ql[(size_t)BB * L * C];
__device__ __align__(16) __nv_bfloat16 g_kh[(size_t)BB * L * C], g_kl[(size_t)BB * L * C];
__device__ __align__(16) __nv_bfloat16 g_vh[(size_t)BB * C * L], g_vl[(size_t)BB * C * L];
__device__ __align__(16) __nv_bfloat16 g_ph[(size_t)BB * L * L], g_pl[(size_t)BB * L * L];
__device__ __align__(16) __nv_bfloat16 g_hth[(size_t)BB * L * C], g_htl[(size_t)BB * L * C];

// ---------------- SMEM layout (2-buffer, 97KB, 2 CTAs/SM) ----------------
#define SM_PTR    0
#define SM_FULL0  8
#define SM_FULL1  16
#define SM_MMA0   24
#define SM_MMA1   32
#define SM_A      1024
#define SM_B      (1024 + 32768)
#define SMEMSZ    (1024 + 32768 + 65536)
#define CHUNK_BYTES 49152u   // A 16KB + B 32KB

#define IDESC_BF16 0x8400490u

// ---------------- fold-proof bf16 hi/lo split ----------------
__device__ __forceinline__ void split_bf16(float v, uint16_t& hb, uint16_t& lb) {
    float hf, r;
    asm("cvt.rn.bf16.f32 %0, %1;" : "=h"(hb) : "f"(v));
    asm("cvt.f32.bf16 %0, %1;"    : "=f"(hf) : "h"(hb));
    asm("sub.rn.f32 %0, %1, %2;"  : "=f"(r)  : "f"(v), "f"(hf));
    asm("cvt.rn.bf16.f32 %0, %1;" : "=h"(lb) : "f"(r));
}
__device__ __forceinline__ void wsplit2(__nv_bfloat16* h, __nv_bfloat16* l, size_t idx,
                                        float a, float b) {
    uint16_t ha, la, hbb, lbb;
    split_bf16(a, ha, la);
    split_bf16(b, hbb, lbb);
    uint32_t hp = (uint32_t)ha | ((uint32_t)hbb << 16);
    uint32_t lp = (uint32_t)la | ((uint32_t)lbb << 16);
    *(uint32_t*)((char*)h + idx * 2) = hp;
    *(uint32_t*)((char*)l + idx * 2) = lp;
}

// ---------------- tcgen05 / TMA helpers ----------------
__device__ __forceinline__ uint32_t smem_u32(const void* p) {
    uint32_t a;
    asm("{ .reg .u64 t; cvta.to.shared.u64 t, %1; cvt.u32.u64 %0, t; }" : "=r"(a) : "l"(p));
    return a;
}
__device__ __forceinline__ uint64_t make_desc(uint32_t addr) {
    return (2ULL << 61) | (1ULL << 46) | (64ULL << 32) | (1ULL << 16) |
           ((uint64_t)(addr >> 4) & 0x3FFF);
}
__device__ __forceinline__ void tc_alloc(uint32_t sptr) {
#if TC_OK
    asm volatile("tcgen05.alloc.cta_group::1.sync.aligned.shared::cta.b32 [%0], %1;"
                 :: "r"(sptr), "r"(256u) : "memory");
    asm volatile("tcgen05.relinquish_alloc_permit.cta_group::1.sync.aligned;");
#endif
}
__device__ __forceinline__ void tc_dealloc(uint32_t tmem) {
#if TC_OK
    asm volatile("tcgen05.dealloc.cta_group::1.sync.aligned.b32 %0, %1;" :: "r"(tmem), "r"(256u));
#endif
}
__device__ __forceinline__ void mma_bf16(uint32_t d, uint64_t ad, uint64_t bd, bool acc) {
#if TC_OK
    uint32_t e = acc ? 1u : 0u;
    asm volatile(
        "{\n\t.reg .pred p;\n\tsetp.ne.u32 p, %4, 0;\n\t"
        "tcgen05.mma.cta_group::1.kind::f16 [%0], %1, %2, %3, {%5, %5, %5, %5}, p;\n\t}"
        :: "r"(d), "l"(ad), "l"(bd), "r"(IDESC_BF16), "r"(e), "r"(0u) : "memory");
#endif
}
__device__ __forceinline__ void tc_commit(uint32_t mbar) {
#if TC_OK
    asm volatile("tcgen05.commit.cta_group::1.mbarrier::arrive::one.shared::cluster.b64 [%0];"
                 :: "r"(mbar) : "memory");
#endif
}
__device__ __forceinline__ void tc_fence_after() {
#if TC_OK
    asm volatile("tcgen05.fence::after_thread_sync;" ::: "memory");
#endif
}
__device__ __forceinline__ void ldtm32(uint32_t* r, uint32_t addr) {
#if TC_OK
    asm volatile(
        "tcgen05.ld.sync.aligned.32x32b.x32.b32 "
        "{%0, %1, %2, %3, %4, %5, %6, %7, "
        " %8, %9, %10, %11, %12, %13, %14, %15, "
        " %16, %17, %18, %19, %20, %21, %22, %23, "
        " %24, %25, %26, %27, %28, %29, %30, %31}, [%32];"
        : "=r"(r[0]),  "=r"(r[1]),  "=r"(r[2]),  "=r"(r[3]),
          "=r"(r[4]),  "=r"(r[5]),  "=r"(r[6]),  "=r"(r[7]),
          "=r"(r[8]),  "=r"(r[9]),  "=r"(r[10]), "=r"(r[11]),
          "=r"(r[12]), "=r"(r[13]), "=r"(r[14]), "=r"(r[15]),
          "=r"(r[16]), "=r"(r[17]), "=r"(r[18]), "=r"(r[19]),
          "=r"(r[20]), "=r"(r[21]), "=r"(r[22]), "=r"(r[23]),
          "=r"(r[24]), "=r"(r[25]), "=r"(r[26]), "=r"(r[27]),
          "=r"(r[28]), "=r"(r[29]), "=r"(r[30]), "=r"(r[31])
        : "r"(addr));
    asm volatile("tcgen05.wait::ld.sync.aligned;" ::: "memory");
#else
#pragma unroll
    for (int i = 0; i < 32; i++) r[i] = 0;
#endif
}
__device__ __forceinline__ void mbar_init(uint32_t a) {
    asm volatile("mbarrier.init.shared.b64 [%0], %1;" :: "r"(a), "r"(1u) : "memory");
}
__device__ __forceinline__ void mbar_wait(uint32_t a, int parity) {
    asm volatile(
        "{\n\t.reg .pred P;\n"
        "W_%=:\n\t"
        "mbarrier.try_wait.parity.acquire.cta.shared::cta.b64 P, [%0], %1, 0x989680;\n\t"
        "@P bra.uni D_%=;\n\t"
        "bra.uni W_%=;\n"
        "D_%=:\n\t}"
        :: "r"(a), "r"(parity) : "memory");
}
__device__ __forceinline__ void mbar_expect(uint32_t a, uint32_t bytes) {
    asm volatile("mbarrier.arrive.expect_tx.shared.b64 _, [%0], %1;"
                 :: "r"(a), "r"(bytes) : "memory");
}
__device__ __forceinline__ void tma_tile(const CUtensorMap* m, uint32_t dst,
                                         int kx, int row, uint32_t mbar) {
    asm volatile(
        "cp.async.bulk.tensor.3d.shared::cta.global.tile.mbarrier::complete_tx::bytes "
        "[%0], [%1, {%2, %3, %4}], [%5];"
        :: "r"(dst), "l"(m), "r"(kx), "r"(row), "r"(0), "r"(mbar) : "memory");
}

// ---------------- TMA-driven pipelined GEMM3 (single-thread driver) ----------------
// D[128x256] = Ah*Bh^T + Al*Bh^T + Ah*Bl^T over K = nseg*64 per pass
__device__ __forceinline__ uint32_t run_gemm3(const CUtensorMap* Ah, const CUtensorMap* Al,
                                              const CUtensorMap* Bh, const CUtensorMap* Bl,
                                              int arow, int brow, int kbase, int nseg,
                                              char* smem) {
    const int t = threadIdx.x;
    const int nch = 3 * nseg;
    uint32_t sb = smem_u32(smem);
    if (t < 32) tc_alloc(sb + SM_PTR);
    if (t == 0) {
        mbar_init(sb + SM_FULL0); mbar_init(sb + SM_FULL1);
        mbar_init(sb + SM_MMA0);  mbar_init(sb + SM_MMA1);
        asm volatile("fence.proxy.async.shared::cta;" ::: "memory");
    }
    __syncthreads();
    uint32_t tmem;
    asm volatile("ld.shared.b32 %0, [%1];" : "=r"(tmem) : "r"(sb + SM_PTR));

    if (t == 0) {
        int phF[2] = {0, 0}, phM[2] = {0, 0};
        // prologue: chunk 0 (seg 0 -> Ah,Bh)
        mbar_expect(sb + SM_FULL0, CHUNK_BYTES);
        tma_tile(Ah, sb + SM_A, kbase, arow, sb + SM_FULL0);
        tma_tile(Bh, sb + SM_B, kbase, brow, sb + SM_FULL0);

        for (int ck = 0; ck < nch; ck++) {
            const int pb = ck & 1;
            if (ck + 1 < nch) {
                const int nb = pb ^ 1;
                if (ck >= 1) { mbar_wait(sb + SM_MMA0 + 8 * nb, phM[nb]); phM[nb] ^= 1; }
                int cn = ck + 1;
                int seg = (cn >= nseg) + (cn >= 2 * nseg);
                const CUtensorMap* mA = (seg == 1) ? Al : Ah;
                const CUtensorMap* mB = (seg == 2) ? Bl : Bh;
                int kx = kbase + (cn - seg * nseg) * 64;
                mbar_expect(sb + SM_FULL0 + 8 * nb, CHUNK_BYTES);
                tma_tile(mA, sb + SM_A + nb * 16384, kx, arow, sb + SM_FULL0 + 8 * nb);
                tma_tile(mB, sb + SM_B + nb * 32768, kx, brow, sb + SM_FULL0 + 8 * nb);
            }
            mbar_wait(sb + SM_FULL0 + 8 * pb, phF[pb]);
            phF[pb] ^= 1;
            uint64_t ad = make_desc(sb + SM_A + pb * 16384);
            uint64_t bd = make_desc(sb + SM_B + pb * 32768);
#pragma unroll
            for (int s = 0; s < 4; s++)
                mma_bf16(tmem, ad + 2 * s, bd + 2 * s, (ck | s) != 0);
            tc_commit(sb + SM_MMA0 + 8 * pb);
        }
        int m = (nch - 1) & 1;
        mbar_wait(sb + SM_MMA0 + 8 * m, phM[m]);
    }
    __syncthreads();
    tc_fence_after();
    return tmem;
}

__device__ __forceinline__ void gemm_dealloc(uint32_t tmem) {
    __syncthreads();
    if (threadIdx.x < 32) tc_dealloc(tmem);
}

// ---------------- 1) BN stats ----------------
__global__ void __launch_bounds__(256) bn_stats(const float* __restrict__ x,
                                                const float* __restrict__ gamma,
                                                const float* __restrict__ beta) {
    int c = blockIdx.x, t = threadIdx.x;
    float s = 0.f, sq = 0.f;
    for (int b = 0; b < BB; b++) {
        const float* p = x + ((size_t)b * C + c) * L;
        for (int l = t; l < L; l += 256) { float v = p[l]; s += v; sq += v * v; }
    }
    __shared__ float sh0[256], sh1[256];
    sh0[t] = s; sh1[t] = sq;
    __syncthreads();
    for (int o = 128; o > 0; o >>= 1) {
        if (t < o) { sh0[t] += sh0[t + o]; sh1[t] += sh1[t + o]; }
        __syncthreads();
    }
    if (t == 0) {
        const float inv_n = 1.f / (float)(BB * L);
        float mean = sh0[0] * inv_n;
        float var  = sh1[0] * inv_n - mean * mean;
        float rs   = rsqrtf(var + EPSV);
        float sc   = gamma[c] * rs;
        g_scale[c] = sc;
        g_shift[c] = beta[c] - mean * sc;
    }
}

// ---------------- 2) split RAW weights ----------------
__global__ void __launch_bounds__(256) split_weights(const float* __restrict__ wq,
                                                     const float* __restrict__ wk,
                                                     const float* __restrict__ wv,
                                                     const float* __restrict__ wp) {
    int mat = blockIdx.y;
    const float* w = (mat == 0) ? wq : ((mat == 1) ? wk : ((mat == 2) ? wv : wp));
    size_t i = ((size_t)blockIdx.x * 256 + threadIdx.x) * 2;
    float2 v = *(const float2*)(w + i);
    wsplit2(g_wbh + (size_t)mat * C * C, g_wbl + (size_t)mat * C * C, i, v.x, v.y);
}

// ---------------- 3) normalize + transpose + split x ----------------
__global__ void __launch_bounds__(256) prep_xsplit(const float* __restrict__ x) {
    __shared__ float tile[32][33];
    int bi = blockIdx.z;
    int l0 = blockIdx.x * 32, c0 = blockIdx.y * 32;
    int tx = threadIdx.x, ty = threadIdx.y;
#pragma unroll
    for (int j = 0; j < 4; j++) {
        int c = c0 + ty + j * 8;
        float v = x[((size_t)bi * C + c) * L + l0 + tx];
        tile[ty + j * 8][tx] = v * g_scale[c] + g_shift[c];
    }
    __syncthreads();
#pragma unroll
    for (int j = 0; j < 4; j++) {
        int l = l0 + ty + j * 8;
        float v = tile[tx][ty + j * 8];
        uint16_t hb, lb;
        split_bf16(v, hb, lb);
        size_t idx = ((size_t)bi * L + l) * C + c0 + tx;
        *(uint16_t*)&g_xth[idx] = hb;
        *(uint16_t*)&g_xtl[idx] = lb;
    }
}

// ---------------- 4) q/k TC projection ----------------
__global__ void __launch_bounds__(256) qk_gemm_tc(const float* __restrict__ bq,
                                                  const float* __restrict__ bk,
                                                  const __grid_constant__ CUtensorMap mAh,
                                                  const __grid_constant__ CUtensorMap mAl,
                                                  const __grid_constant__ CUtensorMap mBh,
                                                  const __grid_constant__ CUtensorMap mBl) {
    extern __shared__ char smem[];
    int bi = blockIdx.y >> 1, mat = blockIdx.y & 1;
    int l0 = blockIdx.x * 128;
    uint32_t tmem = run_gemm3(&mAh, &mAl, &mBh, &mBl,
                              bi * L + l0, mat * C, 0, 4, smem);

    int t = threadIdx.x, wt = t & 127, wg = t >> 7;
    size_t drow = ((size_t)bi * L + l0 + wt) * C;
    __nv_bfloat16* dh = mat ? g_kh : g_qh;
    __nv_bfloat16* dl = mat ? g_kl : g_ql;
    const float* bias = mat ? bk : bq;
    for (int nbl = 0; nbl < 4; nbl++) {
        int nb = wg * 4 + nbl;
        uint32_t r[32];
        ldtm32(r, tmem + nb * 32);
#pragma unroll
        for (int j = 0; j < 16; j++) {
            int n = nb * 32 + 2 * j;
            wsplit2(dh, dl, drow + n, __uint_as_float(r[2 * j + 0]) + bias[n + 0],
                                      __uint_as_float(r[2 * j + 1]) + bias[n + 1]);
        }
    }
    gemm_dealloc(tmem);
}

// ---------------- 5) v TC projection ----------------
__global__ void __launch_bounds__(256) v_gemm_tc(const float* __restrict__ bv,
                                                 const __grid_constant__ CUtensorMap mAh,
                                                 const __grid_constant__ CUtensorMap mAl,
                                                 const __grid_constant__ CUtensorMap mBh,
                                                 const __grid_constant__ CUtensorMap mBl) {
    extern __shared__ char smem[];
    int bi = blockIdx.z, o0 = blockIdx.y * 128, l0 = blockIdx.x * 256;
    uint32_t tmem = run_gemm3(&mAh, &mAl, &mBh, &mBl,
                              2 * C + o0, bi * L + l0, 0, 4, smem);

    int t = threadIdx.x, wt = t & 127, wg = t >> 7;
    float bias = bv[o0 + wt];
    size_t drow = ((size_t)bi * C + o0 + wt) * L + l0;
    for (int nbl = 0; nbl < 4; nbl++) {
        int nb = wg * 4 + nbl;
        uint32_t r[32];
        ldtm32(r, tmem + nb * 32);
#pragma unroll
        for (int j = 0; j < 16; j++) {
            int n = nb * 32 + 2 * j;
            wsplit2(g_vh, g_vl, drow + n, __uint_as_float(r[2 * j + 0]) + bias,
                                          __uint_as_float(r[2 * j + 1]) + bias);
        }
    }
    gemm_dealloc(tmem);
}

// ---------------- 6) scores TC (per-batch) ----------------
__global__ void __launch_bounds__(256) scores_gemm_tc(int bi0,
                                                      const __grid_constant__ CUtensorMap mAh,
                                                      const __grid_constant__ CUtensorMap mAl,
                                                      const __grid_constant__ CUtensorMap mBh,
                                                      const __grid_constant__ CUtensorMap mBl) {
    extern __shared__ char smem[];
    int bi = bi0, i0 = blockIdx.y * 128, j0 = blockIdx.x * 256;
    uint32_t tmem = run_gemm3(&mAh, &mAl, &mBh, &mBl,
                              bi * L + i0, bi * L + j0, 0, 4, smem);

    int t = threadIdx.x, wt = t & 127, wg = t >> 7;
    float* dst = g_s + ((size_t)bi * L + i0 + wt) * L + j0;
    const float scale = 0.0625f;
    for (int nbl = 0; nbl < 4; nbl++) {
        int nb = wg * 4 + nbl;
        uint32_t r[32];
        ldtm32(r, tmem + nb * 32);
#pragma unroll
        for (int j = 0; j < 8; j++) {
            float4 v;
            v.x = __uint_as_float(r[4 * j + 0]) * scale;
            v.y = __uint_as_float(r[4 * j + 1]) * scale;
            v.z = __uint_as_float(r[4 * j + 2]) * scale;
            v.w = __uint_as_float(r[4 * j + 3]) * scale;
            *(float4*)(dst + nb * 32 + 4 * j) = v;
        }
    }
    gemm_dealloc(tmem);
}

// ---------------- 7) softmax rows (per-batch) -> ph/pl ----------------
__global__ void __launch_bounds__(256) softmax_rows(int bi0) {
    size_t row = (size_t)bi0 * L + blockIdx.x;
    const float* p = g_s + row * (size_t)L;
    const int t = threadIdx.x;
    float2 r[8];
    float mx = -1e30f;
#pragma unroll
    for (int i = 0; i < 8; i++) {
        r[i] = *(const float2*)(p + i * 512 + t * 2);
        mx = fmaxf(mx, fmaxf(r[i].x, r[i].y));
    }
#pragma unroll
    for (int o = 16; o; o >>= 1) mx = fmaxf(mx, __shfl_xor_sync(0xffffffffu, mx, o));
    __shared__ float sm[8];
    if ((t & 31) == 0) sm[t >> 5] = mx;
    __syncthreads();
    float bm = sm[0];
#pragma unroll
    for (int i = 1; i < 8; i++) bm = fmaxf(bm, sm[i]);
    float s = 0.f;
#pragma unroll
    for (int i = 0; i < 8; i++) {
        r[i].x = __expf(r[i].x - bm);
        r[i].y = __expf(r[i].y - bm);
        s += r[i].x + r[i].y;
    }
#pragma unroll
    for (int o = 16; o; o >>= 1) s += __shfl_xor_sync(0xffffffffu, s, o);
    __syncthreads();
    if ((t & 31) == 0) sm[t >> 5] = s;
    __syncthreads();
    float tot = 0.f;
#pragma unroll
    for (int i = 0; i < 8; i++) tot += sm[i];
    float inv = 1.f / tot;
    size_t base = row * (size_t)L;
#pragma unroll
    for (int i = 0; i < 8; i++)
        wsplit2(g_ph, g_pl, base + i * 512 + t * 2, r[i].x * inv, r[i].y * inv);
}

// ---------------- 8) AV TC, split-K (per-batch) ----------------
__global__ void __launch_bounds__(256) av_gemm_tc(int bi0,
                                                  const __grid_constant__ CUtensorMap mAh,
                                                  const __grid_constant__ CUtensorMap mAl,
                                                  const __grid_constant__ CUtensorMap mBh,
                                                  const __grid_constant__ CUtensorMap mBl) {
    extern __shared__ char smem[];
    int bi = bi0, ks = blockIdx.y, i0 = blockIdx.x * 128;
    const int koff = ks * (L / NSPLIT);
    uint32_t tmem = run_gemm3(&mAh, &mAl, &mBh, &mBl,
                              bi * L + i0, bi * C, koff, (L / NSPLIT) / 64, smem);

    int t = threadIdx.x, wt = t & 127, wg = t >> 7;
    float* hb = g_hp[ks] + (size_t)bi * C * L;
    for (int nbl = 0; nbl < 4; nbl++) {
        int nb = wg * 4 + nbl;
        uint32_t r[32];
        ldtm32(r, tmem + nb * 32);
#pragma unroll
        for (int j = 0; j < 32; j++) {
            int c = nb * 32 + j;
            hb[(size_t)c * L + i0 + wt] = __uint_as_float(r[j]);
        }
    }
    gemm_dealloc(tmem);
}

// ---------------- 9) reduce partials + transpose + split h ----------------
__global__ void __launch_bounds__(256) reduce_split_h() {
    __shared__ float tile[32][33];
    int bi = blockIdx.z;
    int l0 = blockIdx.x * 32, c0 = blockIdx.y * 32;
    int tx = threadIdx.x, ty = threadIdx.y;
#pragma unroll
    for (int j = 0; j < 4; j++) {
        int c = c0 + ty + j * 8;
        size_t idx = ((size_t)bi * C + c) * L + l0 + tx;
        float s = g_hp[0][idx] + g_hp[1][idx] + g_hp[2][idx] + g_hp[3][idx];
        tile[ty + j * 8][tx] = s;
    }
    __syncthreads();
#pragma unroll
    for (int j = 0; j < 4; j++) {
        int l = l0 + ty + j * 8;
        float v = tile[tx][ty + j * 8];
        uint16_t hb, lb;
        split_bf16(v, hb, lb);
        size_t idx = ((size_t)bi * L + l) * C + c0 + tx;
        *(uint16_t*)&g_hth[idx] = hb;
        *(uint16_t*)&g_htl[idx] = lb;
    }
}

// ---------------- 10) proj TC + bias + residual ----------------
__global__ void __launch_bounds__(256) proj_gemm_tc(const float* __restrict__ x,
                                                    const float* __restrict__ bp,
                                                    float* __restrict__ out,
                                                    const __grid_constant__ CUtensorMap mAh,
                                                    const __grid_constant__ CUtensorMap mAl,
                                                    const __grid_constant__ CUtensorMap mBh,
                                                    const __grid_constant__ CUtensorMap mBl) {
    extern __shared__ char smem[];
    int bi = blockIdx.z, o0 = blockIdx.y * 128, l0 = blockIdx.x * 256;
    uint32_t tmem = run_gemm3(&mAh, &mAl, &mBh, &mBl,
                              3 * C + o0, bi * L + l0, 0, 4, smem);

    int t = threadIdx.x, wt = t & 127, wg = t >> 7;
    float bias = bp[o0 + wt];
    size_t base = ((size_t)bi * C + o0 + wt) * L + l0;
    for (int nbl = 0; nbl < 4; nbl++) {
        int nb = wg * 4 + nbl;
        uint32_t r[32];
        ldtm32(r, tmem + nb * 32);
#pragma unroll
        for (int j = 0; j < 8; j++) {
            float4 xr = *(const float4*)(x + base + nb * 32 + 4 * j);
            float4 v;
            v.x = __uint_as_float(r[4 * j + 0]) + bias + xr.x;
            v.y = __uint_as_float(r[4 * j + 1]) + bias + xr.y;
            v.z = __uint_as_float(r[4 * j + 2]) + bias + xr.z;
            v.w = __uint_as_float(r[4 * j + 3]) + bias + xr.w;
            *(float4*)(out + base + nb * 32 + 4 * j) = v;
        }
    }
    gemm_dealloc(tmem);
}

// ---------------- host: tensormap construction + launch ----------------
typedef CUresult (*EncodeTiledFn)(CUtensorMap*, CUtensorMapDataType, cuuint32_t, void*,
                                  const cuuint64_t*, const cuuint64_t*, const cuuint32_t*,
                                  const cuuint32_t*, CUtensorMapInterleave, CUtensorMapSwizzle,
                                  CUtensorMapL2promotion, CUtensorMapFloatOOBfill);

// map indices
enum { M_XTA_H, M_XTA_L, M_XTB_H, M_XTB_L, M_WBA_H, M_WBA_L, M_WBB_H, M_WBB_L,
       M_QA_H, M_QA_L, M_KB_H, M_KB_L, M_PA_H, M_PA_L, M_VB_H, M_VB_L,
       M_HB_H, M_HB_L, M_COUNT };
static CUtensorMap h_maps[M_COUNT];

static void make_map(EncodeTiledFn enc, CUtensorMap* m, void* base,
                     uint64_t dim0, uint64_t rows, uint32_t box_rows) {
    cuuint64_t dims[3]    = {dim0, rows, 1};
    cuuint64_t strides[2] = {dim0 * 2, dim0 * 2 * rows};
    cuuint32_t box[3]     = {64, box_rows, 1};
    cuuint32_t es[3]      = {1, 1, 1};
    enc(m, CU_TENSOR_MAP_DATA_TYPE_BFLOAT16, 3, base, dims, strides, box, es,
        CU_TENSOR_MAP_INTERLEAVE_NONE, CU_TENSOR_MAP_SWIZZLE_128B,
        CU_TENSOR_MAP_L2_PROMOTION_L2_128B, CU_TENSOR_MAP_FLOAT_OOB_FILL_NONE);
}

extern "C" void kernel_launch(void* const* d_in, const int* in_sizes, int n_in,
                              void* d_out, int out_size) {
    const float* x     = (const float*)d_in[0];
    const float* gamma = (const float*)d_in[1];
    const float* beta  = (const float*)d_in[2];
    const float* wq    = (const float*)d_in[3];
    const float* bq    = (const float*)d_in[4];
    const float* wk    = (const float*)d_in[5];
    const float* bk    = (const float*)d_in[6];
    const float* wv    = (const float*)d_in[7];
    const float* bv    = (const float*)d_in[8];
    const float* wp    = (const float*)d_in[9];
    const float* bp    = (const float*)d_in[10];
    float* out = (float*)d_out;

    static bool inited = false;
    static cudaStream_t s1, s2, s3;
    static cudaEvent_t e0, ePrep, eW, eQK, eV, eC1, eC2, eC3;
    if (!inited) {
        cudaStreamCreateWithFlags(&s1, cudaStreamNonBlocking);
        cudaStreamCreateWithFlags(&s2, cudaStreamNonBlocking);
        cudaStreamCreateWithFlags(&s3, cudaStreamNonBlocking);
        cudaEventCreateWithFlags(&e0,    cudaEventDisableTiming);
        cudaEventCreateWithFlags(&ePrep, cudaEventDisableTiming);
        cudaEventCreateWithFlags(&eW,    cudaEventDisableTiming);
        cudaEventCreateWithFlags(&eQK,   cudaEventDisableTiming);
        cudaEventCreateWithFlags(&eV,    cudaEventDisableTiming);
        cudaEventCreateWithFlags(&eC1,   cudaEventDisableTiming);
        cudaEventCreateWithFlags(&eC2,   cudaEventDisableTiming);
        cudaEventCreateWithFlags(&eC3,   cudaEventDisableTiming);
        cudaFuncSetAttribute(qk_gemm_tc,     cudaFuncAttributeMaxDynamicSharedMemorySize, SMEMSZ);
        cudaFuncSetAttribute(v_gemm_tc,      cudaFuncAttributeMaxDynamicSharedMemorySize, SMEMSZ);
        cudaFuncSetAttribute(scores_gemm_tc, cudaFuncAttributeMaxDynamicSharedMemorySize, SMEMSZ);
        cudaFuncSetAttribute(av_gemm_tc,     cudaFuncAttributeMaxDynamicSharedMemorySize, SMEMSZ);
        cudaFuncSetAttribute(proj_gemm_tc,   cudaFuncAttributeMaxDynamicSharedMemorySize, SMEMSZ);

        EncodeTiledFn enc = nullptr;
        cudaDriverEntryPointQueryResult st;
        cudaGetDriverEntryPointByVersion("cuTensorMapEncodeTiled", (void**)&enc, 12000,
                                         cudaEnableDefault, &st);
        void *pxh, *pxl, *pwh, *pwl, *pqh, *pql, *pkh, *pkl, *pph, *ppl, *pvh, *pvl, *phh, *phl;
        cudaGetSymbolAddress(&pxh, g_xth); cudaGetSymbolAddress(&pxl, g_xtl);
        cudaGetSymbolAddress(&pwh, g_wbh); cudaGetSymbolAddress(&pwl, g_wbl);
        cudaGetSymbolAddress(&pqh, g_qh);  cudaGetSymbolAddress(&pql, g_ql);
        cudaGetSymbolAddress(&pkh, g_kh);  cudaGetSymbolAddress(&pkl, g_kl);
        cudaGetSymbolAddress(&pph, g_ph);  cudaGetSymbolAddress(&ppl, g_pl);
        cudaGetSymbolAddress(&pvh, g_vh);  cudaGetSymbolAddress(&pvl, g_vl);
        cudaGetSymbolAddress(&phh, g_hth); cudaGetSymbolAddress(&phl, g_htl);

        make_map(enc, &h_maps[M_XTA_H], pxh, C, (uint64_t)BB * L, 128);
        make_map(enc, &h_maps[M_XTA_L], pxl, C, (uint64_t)BB * L, 128);
        make_map(enc, &h_maps[M_XTB_H], pxh, C, (uint64_t)BB * L, 256);
        make_map(enc, &h_maps[M_XTB_L], pxl, C, (uint64_t)BB * L, 256);
        make_map(enc, &h_maps[M_WBA_H], pwh, C, 4 * C, 128);
        make_map(enc, &h_maps[M_WBA_L], pwl, C, 4 * C, 128);
        make_map(enc, &h_maps[M_WBB_H], pwh, C, 4 * C, 256);
        make_map(enc, &h_maps[M_WBB_L], pwl, C, 4 * C, 256);
        make_map(enc, &h_maps[M_QA_H],  pqh, C, (uint64_t)BB * L, 128);
        make_map(enc, &h_maps[M_QA_L],  pql, C, (uint64_t)BB * L, 128);
        make_map(enc, &h_maps[M_KB_H],  pkh, C, (uint64_t)BB * L, 256);
        make_map(enc, &h_maps[M_KB_L],  pkl, C, (uint64_t)BB * L, 256);
        make_map(enc, &h_maps[M_PA_H],  pph, L, (uint64_t)BB * L, 128);
        make_map(enc, &h_maps[M_PA_L],  ppl, L, (uint64_t)BB * L, 128);
        make_map(enc, &h_maps[M_VB_H],  pvh, L, (uint64_t)BB * C, 256);
        make_map(enc, &h_maps[M_VB_L],  pvl, L, (uint64_t)BB * C, 256);
        make_map(enc, &h_maps[M_HB_H],  phh, C, (uint64_t)BB * L, 256);
        make_map(enc, &h_maps[M_HB_L],  phl, C, (uint64_t)BB * L, 256);
        inited = true;
    }

    // fork: split_weights on s1
    cudaEventRecord(e0, 0);
    cudaStreamWaitEvent(s1, e0, 0);
    split_weights<<<dim3((C * C / 2) / 256, 4), 256, 0, s1>>>(wq, wk, wv, wp);
    cudaEventRecord(eW, s1);

    bn_stats<<<C, 256>>>(x, gamma, beta);
    prep_xsplit<<<dim3(L / 32, C / 32, BB), dim3(32, 8)>>>(x);
    cudaEventRecord(ePrep, 0);

    cudaStreamWaitEvent(0, eW, 0);
    qk_gemm_tc<<<dim3(L / 128, BB * 2), 256, SMEMSZ, 0>>>(bq, bk,
        h_maps[M_XTA_H], h_maps[M_XTA_L], h_maps[M_WBB_H], h_maps[M_WBB_L]);
    cudaEventRecord(eQK, 0);

    cudaStreamWaitEvent(s1, ePrep, 0);
    v_gemm_tc<<<dim3(L / 256, C / 128, BB), 256, SMEMSZ, s1>>>(bv,
        h_maps[M_WBA_H], h_maps[M_WBA_L], h_maps[M_XTB_H], h_maps[M_XTB_L]);
    cudaEventRecord(eV, s1);

    // per-batch chains
    cudaStreamWaitEvent(0, eV, 0);
    scores_gemm_tc<<<dim3(L / 256, L / 128, 1), 256, SMEMSZ, 0>>>(0,
        h_maps[M_QA_H], h_maps[M_QA_L], h_maps[M_KB_H], h_maps[M_KB_L]);
    softmax_rows<<<L, 256, 0, 0>>>(0);
    av_gemm_tc<<<dim3(L / 128, NSPLIT, 1), 256, SMEMSZ, 0>>>(0,
        h_maps[M_PA_H], h_maps[M_PA_L], h_maps[M_VB_H], h_maps[M_VB_L]);

    cudaStreamWaitEvent(s1, eQK, 0);
    scores_gemm_tc<<<dim3(L / 256, L / 128, 1), 256, SMEMSZ, s1>>>(1,
        h_maps[M_QA_H], h_maps[M_QA_L], h_maps[M_KB_H], h_maps[M_KB_L]);
    softmax_rows<<<L, 256, 0, s1>>>(1);
    av_gemm_tc<<<dim3(L / 128, NSPLIT, 1), 256, SMEMSZ, s1>>>(1,
        h_maps[M_PA_H], h_maps[M_PA_L], h_maps[M_VB_H], h_maps[M_VB_L]);
    cudaEventRecord(eC1, s1);

    cudaStreamWaitEvent(s2, eQK, 0);
    cudaStreamWaitEvent(s2, eV, 0);
    scores_gemm_tc<<<dim3(L / 256, L / 128, 1), 256, SMEMSZ, s2>>>(2,
        h_maps[M_QA_H], h_maps[M_QA_L], h_maps[M_KB_H], h_maps[M_KB_L]);
    softmax_rows<<<L, 256, 0, s2>>>(2);
    av_gemm_tc<<<dim3(L / 128, NSPLIT, 1), 256, SMEMSZ, s2>>>(2,
        h_maps[M_PA_H], h_maps[M_PA_L], h_maps[M_VB_H], h_maps[M_VB_L]);
    cudaEventRecord(eC2, s2);

    cudaStreamWaitEvent(s3, eQK, 0);
    cudaStreamWaitEvent(s3, eV, 0);
    scores_gemm_tc<<<dim3(L / 256, L / 128, 1), 256, SMEMSZ, s3>>>(3,
        h_maps[M_QA_H], h_maps[M_QA_L], h_maps[M_KB_H], h_maps[M_KB_L]);
    softmax_rows<<<L, 256, 0, s3>>>(3);
    av_gemm_tc<<<dim3(L / 128, NSPLIT, 1), 256, SMEMSZ, s3>>>(3,
        h_maps[M_PA_H], h_maps[M_PA_L], h_maps[M_VB_H], h_maps[M_VB_L]);
    cudaEventRecord(eC3, s3);

    cudaStreamWaitEvent(0, eC1, 0);
    cudaStreamWaitEvent(0, eC2, 0);
    cudaStreamWaitEvent(0, eC3, 0);
    reduce_split_h<<<dim3(L / 32, C / 32, BB), dim3(32, 8)>>>();
    proj_gemm_tc<<<dim3(L / 256, C / 128, BB), 256, SMEMSZ>>>(x, bp, out,
        h_maps[M_WBA_H], h_maps[M_WBA_L], h_maps[M_HB_H], h_maps[M_HB_L]);
}

// round 15
// speedup vs baseline: 1.3466x; 1.0684x over previous
#include <cuda_runtime.h>
#include <cuda_bf16.h>
#include <cuda.h>
#include <cstdint>

#define BB 4
#define C 256
#define L 4096
#define EPSV 1e-5f
#define NSPLIT 4
#define K2C (2 * C)
#define K2L (2 * L)

#if defined(__CUDA_ARCH_FEAT_SM103_ALL) || defined(__CUDA_ARCH_FEAT_SM100_ALL) || defined(__CUDA_ARCH_FAMILY_SPECIFIC__)
#define TC_OK 1
#else
#define TC_OK 0
#endif

// ---------------- device scratch: hi|lo packed along K ----------------
__device__ float g_scale[C];
__device__ float g_shift[C];
__device__ __align__(16) __nv_bfloat16 g_wb[4 * C * K2C];              // [mat*C+o][2C]
__device__ __align__(16) __nv_bfloat16 g_xt[(size_t)BB * L * K2C];     // [b*L+l][2C]
__device__ float g_s[(size_t)BB * L * L];
__device__ float g_hp[NSPLIT][(size_t)BB * C * L];
__device__ __align__(16) __nv_bfloat16 g_q[(size_t)BB * L * K2C];
__device__ __align__(16) __nv_bfloat16 g_k[(size_t)BB * L * K2C];
__device__ __align__(16) __nv_bfloat16 g_v[(size_t)BB * C * K2L];      // [b*C+c][2L]
__device__ __align__(16) __nv_bfloat16 g_p[(size_t)BB * L * K2L];      // [b*L+i][2L]
__device__ __align__(16) __nv_bfloat16 g_ht[(size_t)BB * L * K2C];

// ---------------- SMEM: 4 buffers x (A 16KB + B 32KB) = 192KB, 1 CTA/SM ----------------
#define SM_PTR    0
#define SM_FULL   8            // 4 mbars
#define SM_MMA    40           // 4 mbars
#define SM_A      1024
#define SM_B      (1024 + 65536)
#define SMEMSZ    (1024 + 65536 + 131072)
#define CHUNK_BYTES 49152u

#define IDESC_BF16 0x8400490u

// ---------------- fold-proof bf16 hi/lo split ----------------
__device__ __forceinline__ void split_bf16(float v, uint16_t& hb, uint16_t& lb) {
    float hf, r;
    asm("cvt.rn.bf16.f32 %0, %1;" : "=h"(hb) : "f"(v));
    asm("cvt.f32.bf16 %0, %1;"    : "=f"(hf) : "h"(hb));
    asm("sub.rn.f32 %0, %1, %2;"  : "=f"(r)  : "f"(v), "f"(hf));
    asm("cvt.rn.bf16.f32 %0, %1;" : "=h"(lb) : "f"(r));
}
// write 2 consecutive elements: hi at h[idx], lo at l[idx] (h/l may be same array +K offset)
__device__ __forceinline__ void wsplit2(__nv_bfloat16* h, __nv_bfloat16* l, size_t idx,
                                        float a, float b) {
    uint16_t ha, la, hbb, lbb;
    split_bf16(a, ha, la);
    split_bf16(b, hbb, lbb);
    uint32_t hp = (uint32_t)ha | ((uint32_t)hbb << 16);
    uint32_t lp = (uint32_t)la | ((uint32_t)lbb << 16);
    *(uint32_t*)((char*)h + idx * 2) = hp;
    *(uint32_t*)((char*)l + idx * 2) = lp;
}

// ---------------- tcgen05 / TMA helpers ----------------
__device__ __forceinline__ uint32_t smem_u32(const void* p) {
    uint32_t a;
    asm("{ .reg .u64 t; cvta.to.shared.u64 t, %1; cvt.u32.u64 %0, t; }" : "=r"(a) : "l"(p));
    return a;
}
__device__ __forceinline__ uint64_t make_desc(uint32_t addr) {
    return (2ULL << 61) | (1ULL << 46) | (64ULL << 32) | (1ULL << 16) |
           ((uint64_t)(addr >> 4) & 0x3FFF);
}
__device__ __forceinline__ void tc_alloc(uint32_t sptr) {
#if TC_OK
    asm volatile("tcgen05.alloc.cta_group::1.sync.aligned.shared::cta.b32 [%0], %1;"
                 :: "r"(sptr), "r"(256u) : "memory");
    asm volatile("tcgen05.relinquish_alloc_permit.cta_group::1.sync.aligned;");
#endif
}
__device__ __forceinline__ void tc_dealloc(uint32_t tmem) {
#if TC_OK
    asm volatile("tcgen05.dealloc.cta_group::1.sync.aligned.b32 %0, %1;" :: "r"(tmem), "r"(256u));
#endif
}
__device__ __forceinline__ void mma_bf16(uint32_t d, uint64_t ad, uint64_t bd, bool acc) {
#if TC_OK
    uint32_t e = acc ? 1u : 0u;
    asm volatile(
        "{\n\t.reg .pred p;\n\tsetp.ne.u32 p, %4, 0;\n\t"
        "tcgen05.mma.cta_group::1.kind::f16 [%0], %1, %2, %3, {%5, %5, %5, %5}, p;\n\t}"
        :: "r"(d), "l"(ad), "l"(bd), "r"(IDESC_BF16), "r"(e), "r"(0u) : "memory");
#endif
}
__device__ __forceinline__ void tc_commit(uint32_t mbar) {
#if TC_OK
    asm volatile("tcgen05.commit.cta_group::1.mbarrier::arrive::one.shared::cluster.b64 [%0];"
                 :: "r"(mbar) : "memory");
#endif
}
__device__ __forceinline__ void tc_fence_after() {
#if TC_OK
    asm volatile("tcgen05.fence::after_thread_sync;" ::: "memory");
#endif
}
__device__ __forceinline__ void ldtm32(uint32_t* r, uint32_t addr) {
#if TC_OK
    asm volatile(
        "tcgen05.ld.sync.aligned.32x32b.x32.b32 "
        "{%0, %1, %2, %3, %4, %5, %6, %7, "
        " %8, %9, %10, %11, %12, %13, %14, %15, "
        " %16, %17, %18, %19, %20, %21, %22, %23, "
        " %24, %25, %26, %27, %28, %29, %30, %31}, [%32];"
        : "=r"(r[0]),  "=r"(r[1]),  "=r"(r[2]),  "=r"(r[3]),
          "=r"(r[4]),  "=r"(r[5]),  "=r"(r[6]),  "=r"(r[7]),
          "=r"(r[8]),  "=r"(r[9]),  "=r"(r[10]), "=r"(r[11]),
          "=r"(r[12]), "=r"(r[13]), "=r"(r[14]), "=r"(r[15]),
          "=r"(r[16]), "=r"(r[17]), "=r"(r[18]), "=r"(r[19]),
          "=r"(r[20]), "=r"(r[21]), "=r"(r[22]), "=r"(r[23]),
          "=r"(r[24]), "=r"(r[25]), "=r"(r[26]), "=r"(r[27]),
          "=r"(r[28]), "=r"(r[29]), "=r"(r[30]), "=r"(r[31])
        : "r"(addr));
    asm volatile("tcgen05.wait::ld.sync.aligned;" ::: "memory");
#else
#pragma unroll
    for (int i = 0; i < 32; i++) r[i] = 0;
#endif
}
__device__ __forceinline__ void mbar_init(uint32_t a) {
    asm volatile("mbarrier.init.shared.b64 [%0], %1;" :: "r"(a), "r"(1u) : "memory");
}
__device__ __forceinline__ void mbar_wait(uint32_t a, int parity) {
    asm volatile(
        "{\n\t.reg .pred P;\n"
        "W_%=:\n\t"
        "mbarrier.try_wait.parity.acquire.cta.shared::cta.b64 P, [%0], %1, 0x989680;\n\t"
        "@P bra.uni D_%=;\n\t"
        "bra.uni W_%=;\n"
        "D_%=:\n\t}"
        :: "r"(a), "r"(parity) : "memory");
}
__device__ __forceinline__ void mbar_expect(uint32_t a, uint32_t bytes) {
    asm volatile("mbarrier.arrive.expect_tx.shared.b64 _, [%0], %1;"
                 :: "r"(a), "r"(bytes) : "memory");
}
__device__ __forceinline__ void tma_tile(const CUtensorMap* m, uint32_t dst,
                                         int kx, int row, uint32_t mbar) {
    asm volatile(
        "cp.async.bulk.tensor.3d.shared::cta.global.tile.mbarrier::complete_tx::bytes "
        "[%0], [%1, {%2, %3, %4}], [%5];"
        :: "r"(dst), "l"(m), "r"(kx), "r"(row), "r"(0), "r"(mbar) : "memory");
}

// ---------------- TMA-driven GEMM2: 4 buffers, all deps at distance >= 2 ----------------
// D[128x256] = sum over two K ranges [kb1, kb1+nseg*64) and [kb2, kb2+nseg*64)
__device__ __forceinline__ uint32_t run_gemm2(const CUtensorMap* A, const CUtensorMap* B,
                                              int arow, int brow, int kb1, int kb2,
                                              int nseg, char* smem) {
    const int t = threadIdx.x;
    const int nch = 2 * nseg;
    uint32_t sb = smem_u32(smem);
    if (t < 32) tc_alloc(sb + SM_PTR);
    if (t == 0) {
#pragma unroll
        for (int b = 0; b < 4; b++) { mbar_init(sb + SM_FULL + 8 * b); mbar_init(sb + SM_MMA + 8 * b); }
        asm volatile("fence.proxy.async.shared::cta;" ::: "memory");
    }
    __syncthreads();
    uint32_t tmem;
    asm volatile("ld.shared.b32 %0, [%1];" : "=r"(tmem) : "r"(sb + SM_PTR));

    if (t == 0) {
        // prologue: chunks 0,1 in flight
        for (int c = 0; c < 2 && c < nch; c++) {
            int kx = (c < nseg) ? kb1 + c * 64 : kb2 + (c - nseg) * 64;
            mbar_expect(sb + SM_FULL + 8 * c, CHUNK_BYTES);
            tma_tile(A, sb + SM_A + c * 16384, kx, arow, sb + SM_FULL + 8 * c);
            tma_tile(B, sb + SM_B + c * 32768, kx, brow, sb + SM_FULL + 8 * c);
        }
        for (int ck = 0; ck < nch; ck++) {
            const int pb = ck & 3;
            const int cf = ck + 2;
            if (cf < nch) {
                if (ck >= 2)   // buffer (cf&3) held chunk ck-2
                    mbar_wait(sb + SM_MMA + 8 * ((ck - 2) & 3), ((ck - 2) >> 2) & 1);
                int bf = cf & 3;
                int kx = (cf < nseg) ? kb1 + cf * 64 : kb2 + (cf - nseg) * 64;
                mbar_expect(sb + SM_FULL + 8 * bf, CHUNK_BYTES);
                tma_tile(A, sb + SM_A + bf * 16384, kx, arow, sb + SM_FULL + 8 * bf);
                tma_tile(B, sb + SM_B + bf * 32768, kx, brow, sb + SM_FULL + 8 * bf);
            }
            mbar_wait(sb + SM_FULL + 8 * pb, (ck >> 2) & 1);
            uint64_t ad = make_desc(sb + SM_A + pb * 16384);
            uint64_t bd = make_desc(sb + SM_B + pb * 32768);
#pragma unroll
            for (int s = 0; s < 4; s++)
                mma_bf16(tmem, ad + 2 * s, bd + 2 * s, (ck | s) != 0);
            tc_commit(sb + SM_MMA + 8 * pb);
        }
        // last commit tracks all prior MMAs
        mbar_wait(sb + SM_MMA + 8 * ((nch - 1) & 3), ((nch - 1) >> 2) & 1);
    }
    __syncthreads();
    tc_fence_after();
    return tmem;
}

__device__ __forceinline__ void gemm_dealloc(uint32_t tmem) {
    __syncthreads();
    if (threadIdx.x < 32) tc_dealloc(tmem);
}

// ---------------- 1) BN stats ----------------
__global__ void __launch_bounds__(256) bn_stats(const float* __restrict__ x,
                                                const float* __restrict__ gamma,
                                                const float* __restrict__ beta) {
    int c = blockIdx.x, t = threadIdx.x;
    float s = 0.f, sq = 0.f;
    for (int b = 0; b < BB; b++) {
        const float* p = x + ((size_t)b * C + c) * L;
        for (int l = t; l < L; l += 256) { float v = p[l]; s += v; sq += v * v; }
    }
    __shared__ float sh0[256], sh1[256];
    sh0[t] = s; sh1[t] = sq;
    __syncthreads();
    for (int o = 128; o > 0; o >>= 1) {
        if (t < o) { sh0[t] += sh0[t + o]; sh1[t] += sh1[t + o]; }
        __syncthreads();
    }
    if (t == 0) {
        const float inv_n = 1.f / (float)(BB * L);
        float mean = sh0[0] * inv_n;
        float var  = sh1[0] * inv_n - mean * mean;
        float rs   = rsqrtf(var + EPSV);
        float sc   = gamma[c] * rs;
        g_scale[c] = sc;
        g_shift[c] = beta[c] - mean * sc;
    }
}

// ---------------- 2) split RAW weights -> packed [hi|lo] rows ----------------
__global__ void __launch_bounds__(256) split_weights(const float* __restrict__ wq,
                                                     const float* __restrict__ wk,
                                                     const float* __restrict__ wv,
                                                     const float* __restrict__ wp) {
    int mat = blockIdx.y;
    const float* w = (mat == 0) ? wq : ((mat == 1) ? wk : ((mat == 2) ? wv : wp));
    size_t i = ((size_t)blockIdx.x * 256 + threadIdx.x) * 2;
    int o = (int)(i / C), cc = (int)(i % C);
    float2 v = *(const float2*)(w + i);
    __nv_bfloat16* rb = g_wb + ((size_t)mat * C + o) * K2C;
    wsplit2(rb, rb + C, cc, v.x, v.y);
}

// ---------------- 3) normalize + transpose + split x ----------------
__global__ void __launch_bounds__(256) prep_xsplit(const float* __restrict__ x) {
    __shared__ float tile[32][33];
    int bi = blockIdx.z;
    int l0 = blockIdx.x * 32, c0 = blockIdx.y * 32;
    int tx = threadIdx.x, ty = threadIdx.y;
#pragma unroll
    for (int j = 0; j < 4; j++) {
        int c = c0 + ty + j * 8;
        float v = x[((size_t)bi * C + c) * L + l0 + tx];
        tile[ty + j * 8][tx] = v * g_scale[c] + g_shift[c];
    }
    __syncthreads();
#pragma unroll
    for (int j = 0; j < 4; j++) {
        int l = l0 + ty + j * 8;
        float v = tile[tx][ty + j * 8];
        uint16_t hb, lb;
        split_bf16(v, hb, lb);
        size_t rb = ((size_t)bi * L + l) * K2C;
        *(uint16_t*)&g_xt[rb + c0 + tx]     = hb;
        *(uint16_t*)&g_xt[rb + C + c0 + tx] = lb;
    }
}

// ---------------- 4) q/k TC projection ----------------
__global__ void __launch_bounds__(256) qk_gemm_tc(const float* __restrict__ bq,
                                                  const float* __restrict__ bk,
                                                  const __grid_constant__ CUtensorMap mA,
                                                  const __grid_constant__ CUtensorMap mB) {
    extern __shared__ char smem[];
    int bi = blockIdx.y >> 1, mat = blockIdx.y & 1;
    int l0 = blockIdx.x * 128;
    uint32_t tmem = run_gemm2(&mA, &mB, bi * L + l0, mat * C, 0, C, 4, smem);

    int t = threadIdx.x, wt = t & 127, wg = t >> 7;
    size_t drow = ((size_t)bi * L + l0 + wt) * K2C;
    __nv_bfloat16* dst = mat ? g_k : g_q;
    const float* bias = mat ? bk : bq;
    for (int nbl = 0; nbl < 4; nbl++) {
        int nb = wg * 4 + nbl;
        uint32_t r[32];
        ldtm32(r, tmem + nb * 32);
#pragma unroll
        for (int j = 0; j < 16; j++) {
            int n = nb * 32 + 2 * j;
            wsplit2(dst + drow, dst + drow + C, n,
                    __uint_as_float(r[2 * j + 0]) + bias[n + 0],
                    __uint_as_float(r[2 * j + 1]) + bias[n + 1]);
        }
    }
    gemm_dealloc(tmem);
}

// ---------------- 5) v TC projection ----------------
__global__ void __launch_bounds__(256) v_gemm_tc(const float* __restrict__ bv,
                                                 const __grid_constant__ CUtensorMap mA,
                                                 const __grid_constant__ CUtensorMap mB) {
    extern __shared__ char smem[];
    int bi = blockIdx.z, o0 = blockIdx.y * 128, l0 = blockIdx.x * 256;
    uint32_t tmem = run_gemm2(&mA, &mB, 2 * C + o0, bi * L + l0, 0, C, 4, smem);

    int t = threadIdx.x, wt = t & 127, wg = t >> 7;
    float bias = bv[o0 + wt];
    size_t drow = ((size_t)bi * C + o0 + wt) * K2L;
    for (int nbl = 0; nbl < 4; nbl++) {
        int nb = wg * 4 + nbl;
        uint32_t r[32];
        ldtm32(r, tmem + nb * 32);
#pragma unroll
        for (int j = 0; j < 16; j++) {
            int n = nb * 32 + 2 * j;
            wsplit2(g_v + drow, g_v + drow + L, l0 + n,
                    __uint_as_float(r[2 * j + 0]) + bias,
                    __uint_as_float(r[2 * j + 1]) + bias);
        }
    }
    gemm_dealloc(tmem);
}

// ---------------- 6) scores TC (per-batch) ----------------
__global__ void __launch_bounds__(256) scores_gemm_tc(int bi0,
                                                      const __grid_constant__ CUtensorMap mA,
                                                      const __grid_constant__ CUtensorMap mB) {
    extern __shared__ char smem[];
    int bi = bi0, i0 = blockIdx.y * 128, j0 = blockIdx.x * 256;
    uint32_t tmem = run_gemm2(&mA, &mB, bi * L + i0, bi * L + j0, 0, C, 4, smem);

    int t = threadIdx.x, wt = t & 127, wg = t >> 7;
    float* dst = g_s + ((size_t)bi * L + i0 + wt) * L + j0;
    const float scale = 0.0625f;
    for (int nbl = 0; nbl < 4; nbl++) {
        int nb = wg * 4 + nbl;
        uint32_t r[32];
        ldtm32(r, tmem + nb * 32);
#pragma unroll
        for (int j = 0; j < 8; j++) {
            float4 v;
            v.x = __uint_as_float(r[4 * j + 0]) * scale;
            v.y = __uint_as_float(r[4 * j + 1]) * scale;
            v.z = __uint_as_float(r[4 * j + 2]) * scale;
            v.w = __uint_as_float(r[4 * j + 3]) * scale;
            *(float4*)(dst + nb * 32 + 4 * j) = v;
        }
    }
    gemm_dealloc(tmem);
}

// ---------------- 7) softmax rows (per-batch) ----------------
__global__ void __launch_bounds__(256) softmax_rows(int bi0) {
    size_t row = (size_t)bi0 * L + blockIdx.x;
    const float* p = g_s + row * (size_t)L;
    const int t = threadIdx.x;
    float2 r[8];
    float mx = -1e30f;
#pragma unroll
    for (int i = 0; i < 8; i++) {
        r[i] = *(const float2*)(p + i * 512 + t * 2);
        mx = fmaxf(mx, fmaxf(r[i].x, r[i].y));
    }
#pragma unroll
    for (int o = 16; o; o >>= 1) mx = fmaxf(mx, __shfl_xor_sync(0xffffffffu, mx, o));
    __shared__ float sm[8];
    if ((t & 31) == 0) sm[t >> 5] = mx;
    __syncthreads();
    float bm = sm[0];
#pragma unroll
    for (int i = 1; i < 8; i++) bm = fmaxf(bm, sm[i]);
    float s = 0.f;
#pragma unroll
    for (int i = 0; i < 8; i++) {
        r[i].x = __expf(r[i].x - bm);
        r[i].y = __expf(r[i].y - bm);
        s += r[i].x + r[i].y;
    }
#pragma unroll
    for (int o = 16; o; o >>= 1) s += __shfl_xor_sync(0xffffffffu, s, o);
    __syncthreads();
    if ((t & 31) == 0) sm[t >> 5] = s;
    __syncthreads();
    float tot = 0.f;
#pragma unroll
    for (int i = 0; i < 8; i++) tot += sm[i];
    float inv = 1.f / tot;
    size_t base = row * (size_t)K2L;
#pragma unroll
    for (int i = 0; i < 8; i++)
        wsplit2(g_p + base, g_p + base + L, i * 512 + t * 2, r[i].x * inv, r[i].y * inv);
}

// ---------------- 8) AV TC, split-K (per-batch) ----------------
__global__ void __launch_bounds__(256) av_gemm_tc(int bi0,
                                                  const __grid_constant__ CUtensorMap mA,
                                                  const __grid_constant__ CUtensorMap mB) {
    extern __shared__ char smem[];
    int bi = bi0, ks = blockIdx.y, i0 = blockIdx.x * 128;
    const int koff = ks * (L / NSPLIT);
    uint32_t tmem = run_gemm2(&mA, &mB, bi * L + i0, bi * C,
                              koff, L + koff, (L / NSPLIT) / 64, smem);

    int t = threadIdx.x, wt = t & 127, wg = t >> 7;
    float* hb = g_hp[ks] + (size_t)bi * C * L;
    for (int nbl = 0; nbl < 4; nbl++) {
        int nb = wg * 4 + nbl;
        uint32_t r[32];
        ldtm32(r, tmem + nb * 32);
#pragma unroll
        for (int j = 0; j < 32; j++) {
            int c = nb * 32 + j;
            hb[(size_t)c * L + i0 + wt] = __uint_as_float(r[j]);
        }
    }
    gemm_dealloc(tmem);
}

// ---------------- 9) reduce partials + transpose + split h ----------------
__global__ void __launch_bounds__(256) reduce_split_h() {
    __shared__ float tile[32][33];
    int bi = blockIdx.z;
    int l0 = blockIdx.x * 32, c0 = blockIdx.y * 32;
    int tx = threadIdx.x, ty = threadIdx.y;
#pragma unroll
    for (int j = 0; j < 4; j++) {
        int c = c0 + ty + j * 8;
        size_t idx = ((size_t)bi * C + c) * L + l0 + tx;
        float s = g_hp[0][idx] + g_hp[1][idx] + g_hp[2][idx] + g_hp[3][idx];
        tile[ty + j * 8][tx] = s;
    }
    __syncthreads();
#pragma unroll
    for (int j = 0; j < 4; j++) {
        int l = l0 + ty + j * 8;
        float v = tile[tx][ty + j * 8];
        uint16_t hb, lb;
        split_bf16(v, hb, lb);
        size_t rb = ((size_t)bi * L + l) * K2C;
        *(uint16_t*)&g_ht[rb + c0 + tx]     = hb;
        *(uint16_t*)&g_ht[rb + C + c0 + tx] = lb;
    }
}

// ---------------- 10) proj TC + bias + residual ----------------
__global__ void __launch_bounds__(256) proj_gemm_tc(const float* __restrict__ x,
                                                    const float* __restrict__ bp,
                                                    float* __restrict__ out,
                                                    const __grid_constant__ CUtensorMap mA,
                                                    const __grid_constant__ CUtensorMap mB) {
    extern __shared__ char smem[];
    int bi = blockIdx.z, o0 = blockIdx.y * 128, l0 = blockIdx.x * 256;
    uint32_t tmem = run_gemm2(&mA, &mB, 3 * C + o0, bi * L + l0, 0, C, 4, smem);

    int t = threadIdx.x, wt = t & 127, wg = t >> 7;
    float bias = bp[o0 + wt];
    size_t base = ((size_t)bi * C + o0 + wt) * L + l0;
    for (int nbl = 0; nbl < 4; nbl++) {
        int nb = wg * 4 + nbl;
        uint32_t r[32];
        ldtm32(r, tmem + nb * 32);
#pragma unroll
        for (int j = 0; j < 8; j++) {
            float4 xr = *(const float4*)(x + base + nb * 32 + 4 * j);
            float4 v;
            v.x = __uint_as_float(r[4 * j + 0]) + bias + xr.x;
            v.y = __uint_as_float(r[4 * j + 1]) + bias + xr.y;
            v.z = __uint_as_float(r[4 * j + 2]) + bias + xr.z;
            v.w = __uint_as_float(r[4 * j + 3]) + bias + xr.w;
            *(float4*)(out + base + nb * 32 + 4 * j) = v;
        }
    }
    gemm_dealloc(tmem);
}

// ---------------- host: tensormaps + launch ----------------
typedef CUresult (*EncodeTiledFn)(CUtensorMap*, CUtensorMapDataType, cuuint32_t, void*,
                                  const cuuint64_t*, const cuuint64_t*, const cuuint32_t*,
                                  const cuuint32_t*, CUtensorMapInterleave, CUtensorMapSwizzle,
                                  CUtensorMapL2promotion, CUtensorMapFloatOOBfill);

enum { M_XT_A, M_XT_B, M_W_A, M_W_B, M_Q_A, M_K_B, M_P_A, M_V_B, M_H_B, M_COUNT };
static CUtensorMap h_maps[M_COUNT];

static void make_map(EncodeTiledFn enc, CUtensorMap* m, void* base,
                     uint64_t dim0, uint64_t rows, uint32_t box_rows) {
    cuuint64_t dims[3]    = {dim0, rows, 1};
    cuuint64_t strides[2] = {dim0 * 2, dim0 * 2 * rows};
    cuuint32_t box[3]     = {64, box_rows, 1};
    cuuint32_t es[3]      = {1, 1, 1};
    enc(m, CU_TENSOR_MAP_DATA_TYPE_BFLOAT16, 3, base, dims, strides, box, es,
        CU_TENSOR_MAP_INTERLEAVE_NONE, CU_TENSOR_MAP_SWIZZLE_128B,
        CU_TENSOR_MAP_L2_PROMOTION_L2_128B, CU_TENSOR_MAP_FLOAT_OOB_FILL_NONE);
}

extern "C" void kernel_launch(void* const* d_in, const int* in_sizes, int n_in,
                              void* d_out, int out_size) {
    const float* x     = (const float*)d_in[0];
    const float* gamma = (const float*)d_in[1];
    const float* beta  = (const float*)d_in[2];
    const float* wq    = (const float*)d_in[3];
    const float* bq    = (const float*)d_in[4];
    const float* wk    = (const float*)d_in[5];
    const float* bk    = (const float*)d_in[6];
    const float* wv    = (const float*)d_in[7];
    const float* bv    = (const float*)d_in[8];
    const float* wp    = (const float*)d_in[9];
    const float* bp    = (const float*)d_in[10];
    float* out = (float*)d_out;

    static bool inited = false;
    static cudaStream_t s1, s2, s3;
    static cudaEvent_t e0, ePrep, eW, eQK, eV, eC1, eC2, eC3;
    if (!inited) {
        cudaStreamCreateWithFlags(&s1, cudaStreamNonBlocking);
        cudaStreamCreateWithFlags(&s2, cudaStreamNonBlocking);
        cudaStreamCreateWithFlags(&s3, cudaStreamNonBlocking);
        cudaEventCreateWithFlags(&e0,    cudaEventDisableTiming);
        cudaEventCreateWithFlags(&ePrep, cudaEventDisableTiming);
        cudaEventCreateWithFlags(&eW,    cudaEventDisableTiming);
        cudaEventCreateWithFlags(&eQK,   cudaEventDisableTiming);
        cudaEventCreateWithFlags(&eV,    cudaEventDisableTiming);
        cudaEventCreateWithFlags(&eC1,   cudaEventDisableTiming);
        cudaEventCreateWithFlags(&eC2,   cudaEventDisableTiming);
        cudaEventCreateWithFlags(&eC3,   cudaEventDisableTiming);
        cudaFuncSetAttribute(qk_gemm_tc,     cudaFuncAttributeMaxDynamicSharedMemorySize, SMEMSZ);
        cudaFuncSetAttribute(v_gemm_tc,      cudaFuncAttributeMaxDynamicSharedMemorySize, SMEMSZ);
        cudaFuncSetAttribute(scores_gemm_tc, cudaFuncAttributeMaxDynamicSharedMemorySize, SMEMSZ);
        cudaFuncSetAttribute(av_gemm_tc,     cudaFuncAttributeMaxDynamicSharedMemorySize, SMEMSZ);
        cudaFuncSetAttribute(proj_gemm_tc,   cudaFuncAttributeMaxDynamicSharedMemorySize, SMEMSZ);

        EncodeTiledFn enc = nullptr;
        cudaDriverEntryPointQueryResult st;
        cudaGetDriverEntryPointByVersion("cuTensorMapEncodeTiled", (void**)&enc, 12000,
                                         cudaEnableDefault, &st);
        void *pxt, *pwb, *pq, *pk, *pp, *pv, *ph;
        cudaGetSymbolAddress(&pxt, g_xt);
        cudaGetSymbolAddress(&pwb, g_wb);
        cudaGetSymbolAddress(&pq, g_q);
        cudaGetSymbolAddress(&pk, g_k);
        cudaGetSymbolAddress(&pp, g_p);
        cudaGetSymbolAddress(&pv, g_v);
        cudaGetSymbolAddress(&ph, g_ht);

        make_map(enc, &h_maps[M_XT_A], pxt, K2C, (uint64_t)BB * L, 128);
        make_map(enc, &h_maps[M_XT_B], pxt, K2C, (uint64_t)BB * L, 256);
        make_map(enc, &h_maps[M_W_A],  pwb, K2C, 4 * C, 128);
        make_map(enc, &h_maps[M_W_B],  pwb, K2C, 4 * C, 256);
        make_map(enc, &h_maps[M_Q_A],  pq,  K2C, (uint64_t)BB * L, 128);
        make_map(enc, &h_maps[M_K_B],  pk,  K2C, (uint64_t)BB * L, 256);
        make_map(enc, &h_maps[M_P_A],  pp,  K2L, (uint64_t)BB * L, 128);
        make_map(enc, &h_maps[M_V_B],  pv,  K2L, (uint64_t)BB * C, 256);
        make_map(enc, &h_maps[M_H_B],  ph,  K2C, (uint64_t)BB * L, 256);
        inited = true;
    }

    cudaEventRecord(e0, 0);
    cudaStreamWaitEvent(s1, e0, 0);
    split_weights<<<dim3((C * C / 2) / 256, 4), 256, 0, s1>>>(wq, wk, wv, wp);
    cudaEventRecord(eW, s1);

    bn_stats<<<C, 256>>>(x, gamma, beta);
    prep_xsplit<<<dim3(L / 32, C / 32, BB), dim3(32, 8)>>>(x);
    cudaEventRecord(ePrep, 0);

    cudaStreamWaitEvent(0, eW, 0);
    qk_gemm_tc<<<dim3(L / 128, BB * 2), 256, SMEMSZ, 0>>>(bq, bk,
        h_maps[M_XT_A], h_maps[M_W_B]);
    cudaEventRecord(eQK, 0);

    cudaStreamWaitEvent(s1, ePrep, 0);
    v_gemm_tc<<<dim3(L / 256, C / 128, BB), 256, SMEMSZ, s1>>>(bv,
        h_maps[M_W_A], h_maps[M_XT_B]);
    cudaEventRecord(eV, s1);

    cudaStreamWaitEvent(0, eV, 0);
    scores_gemm_tc<<<dim3(L / 256, L / 128, 1), 256, SMEMSZ, 0>>>(0,
        h_maps[M_Q_A], h_maps[M_K_B]);
    softmax_rows<<<L, 256, 0, 0>>>(0);
    av_gemm_tc<<<dim3(L / 128, NSPLIT, 1), 256, SMEMSZ, 0>>>(0,
        h_maps[M_P_A], h_maps[M_V_B]);

    cudaStreamWaitEvent(s1, eQK, 0);
    scores_gemm_tc<<<dim3(L / 256, L / 128, 1), 256, SMEMSZ, s1>>>(1,
        h_maps[M_Q_A], h_maps[M_K_B]);
    softmax_rows<<<L, 256, 0, s1>>>(1);
    av_gemm_tc<<<dim3(L / 128, NSPLIT, 1), 256, SMEMSZ, s1>>>(1,
        h_maps[M_P_A], h_maps[M_V_B]);
    cudaEventRecord(eC1, s1);

    cudaStreamWaitEvent(s2, eQK, 0);
    cudaStreamWaitEvent(s2, eV, 0);
    scores_gemm_tc<<<dim3(L / 256, L / 128, 1), 256, SMEMSZ, s2>>>(2,
        h_maps[M_Q_A], h_maps[M_K_B]);
    softmax_rows<<<L, 256, 0, s2>>>(2);
    av_gemm_tc<<<dim3(L / 128, NSPLIT, 1), 256, SMEMSZ, s2>>>(2,
        h_maps[M_P_A], h_maps[M_V_B]);
    cudaEventRecord(eC2, s2);

    cudaStreamWaitEvent(s3, eQK, 0);
    cudaStreamWaitEvent(s3, eV, 0);
    scores_gemm_tc<<<dim3(L / 256, L / 128, 1), 256, SMEMSZ, s3>>>(3,
        h_maps[M_Q_A], h_maps[M_K_B]);
    softmax_rows<<<L, 256, 0, s3>>>(3);
    av_gemm_tc<<<dim3(L / 128, NSPLIT, 1), 256, SMEMSZ, s3>>>(3,
        h_maps[M_P_A], h_maps[M_V_B]);
    cudaEventRecord(eC3, s3);

    cudaStreamWaitEvent(0, eC1, 0);
    cudaStreamWaitEvent(0, eC2, 0);
    cudaStreamWaitEvent(0, eC3, 0);
    reduce_split_h<<<dim3(L / 32, C / 32, BB), dim3(32, 8)>>>();
    proj_gemm_tc<<<dim3(L / 256, C / 128, BB), 256, SMEMSZ>>>(x, bp, out,
        h_maps[M_W_A], h_maps[M_H_B]);
}